// round 1
// baseline (speedup 1.0000x reference)
#include <cuda_runtime.h>
#include <cuda_bf16.h>

// ---------------------------------------------------------------------------
// SHGNN: 2-layer hypergraph GNN + MLP head + log_softmax
//   N_NODES=100000, N_EDGES=50000, D=128, members/edge=16, edges/node=8
//   Layer L: edge = relu(mean16(node[map])); node_new = relu(mean8(edge[map]))
//            node = concat(node, node_new)
//   h = relu(X(512) @ W1(512x256) + b1);  out = log_softmax(h @ W2(256x40) + b2)
// Inputs: 0 node_x[100000,128] f32, 1 nodes_map[800000] i32, 2 edge_batch,
//         3 edges_map[800000] i32, 4 node_batch, 5 W1[512,256], 6 b1[256],
//         7 W2[256,40], 8 b2[40].  Output: [100000,40] f32.
// ---------------------------------------------------------------------------

#define N_NODES 100000
#define N_EDGES 50000
#define M_PAD   100096              // 782 * 128, pad rows stay zero forever

// Scratch (zero-initialized at module load; pad rows never written -> stay 0)
__device__ float g_nodebuf[(size_t)M_PAD * 512];   // [x0 | nx1 | nx2]
__device__ float g_edgebuf[(size_t)N_EDGES * 256]; // layer1 uses cols 0:128
__device__ float g_hbuf[(size_t)M_PAD * 256];

// ---------------------------------------------------------------------------
// packed f32x2 helpers (Blackwell FFMA2 path)
// ---------------------------------------------------------------------------
__device__ __forceinline__ unsigned long long pack2(float lo, float hi) {
    unsigned long long r;
    asm("mov.b64 %0, {%1, %2};" : "=l"(r) : "f"(lo), "f"(hi));
    return r;
}
__device__ __forceinline__ void fma2(unsigned long long& d,
                                     unsigned long long a, unsigned long long b) {
    asm("fma.rn.f32x2 %0, %1, %2, %0;" : "+l"(d) : "l"(a), "l"(b));
}
__device__ __forceinline__ float2 unpack2(unsigned long long v) {
    float2 r;
    asm("mov.b64 {%0, %1}, %2;" : "=f"(r.x), "=f"(r.y) : "l"(v));
    return r;
}

// ---------------------------------------------------------------------------
// Copy node_x (128 cols) into cols [0,128) of nodebuf (stride 512)
// ---------------------------------------------------------------------------
__global__ void copy_x_kernel(const float* __restrict__ x, float* __restrict__ nb) {
    long i = (long)blockIdx.x * blockDim.x + threadIdx.x;  // float4 index
    if (i >= (long)N_NODES * 32) return;
    long r = i >> 5;
    int  c = (int)(i & 31);
    *(float4*)(nb + r * 512 + c * 4) = *(const float4*)(x + r * 128 + c * 4);
}

// ---------------------------------------------------------------------------
// Generic contiguous-segment gather-mean-relu.
// One warp = (segment, 128-col chunk). Lane owns a float4 column slice.
// ---------------------------------------------------------------------------
template<int G>
__global__ void gather_mean_relu(const float* __restrict__ in, int in_stride,
                                 const int* __restrict__ map,
                                 float* __restrict__ out, int out_stride, int out_off,
                                 int n_seg, int n_chunk) {
    int gw   = (int)(((long)blockIdx.x * blockDim.x + threadIdx.x) >> 5);
    int lane = threadIdx.x & 31;
    if (gw >= n_seg * n_chunk) return;
    int seg = gw / n_chunk;
    int ch  = gw - seg * n_chunk;

    int v = 0;
    if (lane < G) v = __ldg(map + (long)seg * G + lane);

    int coloff = ch * 128 + lane * 4;
    float4 acc = make_float4(0.f, 0.f, 0.f, 0.f);
#pragma unroll
    for (int j = 0; j < G; j++) {
        int r = __shfl_sync(0xffffffffu, v, j);
        const float4 t = *(const float4*)(in + (long)r * in_stride + coloff);
        acc.x += t.x; acc.y += t.y; acc.z += t.z; acc.w += t.w;
    }
    const float s = 1.0f / (float)G;
    float4 o;
    o.x = fmaxf(acc.x * s, 0.f);
    o.y = fmaxf(acc.y * s, 0.f);
    o.z = fmaxf(acc.z * s, 0.f);
    o.w = fmaxf(acc.w * s, 0.f);
    *(float4*)(out + (long)seg * out_stride + out_off + coloff) = o;
}

// ---------------------------------------------------------------------------
// GEMM1: H[M,256] = relu(A[M,512] @ W1[512,256] + b1)
// 128x128x16 tiles, 256 threads, 8x8 per thread via f32x2 (rows paired).
// M padded to 100096 (pad rows of A are zero -> no bounds checks).
// ---------------------------------------------------------------------------
__global__ __launch_bounds__(256)
void sgemm1_kernel(const float* __restrict__ A, const float* __restrict__ W,
                   const float* __restrict__ bias, float* __restrict__ H) {
    __shared__ float As[16][128];   // [k][m]  (transposed)
    __shared__ float Bs[16][128];   // [k][n]

    const int tid = threadIdx.x;
    const int tr  = tid >> 4;       // 0..15  -> rows tr*8 .. tr*8+7
    const int tc  = tid & 15;       // 0..15  -> cols tc*8 .. tc*8+7
    const long rowBase = (long)blockIdx.x * 128;
    const int  colBase = blockIdx.y * 128;

    const int aRow = tid >> 2;          // 0..63
    const int aCol = (tid & 3) << 2;    // 0,4,8,12
    const int bRow = tid >> 5;          // 0..7
    const int bCol = (tid & 31) << 2;   // 0..124

    unsigned long long c2[4][8];
#pragma unroll
    for (int i = 0; i < 4; i++)
#pragma unroll
        for (int j = 0; j < 8; j++) c2[i][j] = 0ULL;

    for (int k0 = 0; k0 < 512; k0 += 16) {
        float4 a0 = *(const float4*)(A + (rowBase + aRow) * 512 + k0 + aCol);
        float4 a1 = *(const float4*)(A + (rowBase + aRow + 64) * 512 + k0 + aCol);
        float4 b0 = *(const float4*)(W + (long)(k0 + bRow) * 256 + colBase + bCol);
        float4 b1 = *(const float4*)(W + (long)(k0 + bRow + 8) * 256 + colBase + bCol);
        __syncthreads();
        As[aCol + 0][aRow] = a0.x;  As[aCol + 1][aRow] = a0.y;
        As[aCol + 2][aRow] = a0.z;  As[aCol + 3][aRow] = a0.w;
        As[aCol + 0][aRow + 64] = a1.x;  As[aCol + 1][aRow + 64] = a1.y;
        As[aCol + 2][aRow + 64] = a1.z;  As[aCol + 3][aRow + 64] = a1.w;
        *(float4*)&Bs[bRow][bCol]     = b0;
        *(float4*)&Bs[bRow + 8][bCol] = b1;
        __syncthreads();

#pragma unroll
        for (int kk = 0; kk < 16; kk++) {
            unsigned long long a2[4];
#pragma unroll
            for (int i = 0; i < 4; i++)
                a2[i] = *(const unsigned long long*)&As[kk][tr * 8 + 2 * i];
            float4 blo = *(const float4*)&Bs[kk][tc * 8];
            float4 bhi = *(const float4*)&Bs[kk][tc * 8 + 4];
            unsigned long long bb[8];
            bb[0] = pack2(blo.x, blo.x); bb[1] = pack2(blo.y, blo.y);
            bb[2] = pack2(blo.z, blo.z); bb[3] = pack2(blo.w, blo.w);
            bb[4] = pack2(bhi.x, bhi.x); bb[5] = pack2(bhi.y, bhi.y);
            bb[6] = pack2(bhi.z, bhi.z); bb[7] = pack2(bhi.w, bhi.w);
#pragma unroll
            for (int i = 0; i < 4; i++)
#pragma unroll
                for (int j = 0; j < 8; j++)
                    fma2(c2[i][j], a2[i], bb[j]);
        }
    }

    float bcol[8];
#pragma unroll
    for (int j = 0; j < 8; j++) bcol[j] = bias[colBase + tc * 8 + j];

#pragma unroll
    for (int i = 0; i < 4; i++) {
        float lo[8], hi[8];
#pragma unroll
        for (int j = 0; j < 8; j++) {
            float2 f = unpack2(c2[i][j]);
            lo[j] = fmaxf(f.x + bcol[j], 0.f);
            hi[j] = fmaxf(f.y + bcol[j], 0.f);
        }
        long r0 = rowBase + tr * 8 + 2 * i;
        float4* p0 = (float4*)(H + r0 * 256 + colBase + tc * 8);
        p0[0] = make_float4(lo[0], lo[1], lo[2], lo[3]);
        p0[1] = make_float4(lo[4], lo[5], lo[6], lo[7]);
        float4* p1 = (float4*)(H + (r0 + 1) * 256 + colBase + tc * 8);
        p1[0] = make_float4(hi[0], hi[1], hi[2], hi[3]);
        p1[1] = make_float4(hi[4], hi[5], hi[6], hi[7]);
    }
}

// ---------------------------------------------------------------------------
// GEMM2 + log_softmax: out[row,0:40] = logsoftmax(H[row,:]@W2 + b2)
// Thread-per-row, W2 in smem (broadcast LDS), 40 accumulators in regs.
// ---------------------------------------------------------------------------
__global__ __launch_bounds__(256)
void gemm2_lsm_kernel(const float* __restrict__ H, const float* __restrict__ W2,
                      const float* __restrict__ b2, float* __restrict__ out,
                      int nrows) {
    __shared__ float sW[256 * 40];
    __shared__ float sb[40];
    for (int i = threadIdx.x; i < 256 * 40; i += 256) sW[i] = W2[i];
    if (threadIdx.x < 40) sb[threadIdx.x] = b2[threadIdx.x];
    __syncthreads();

    long row = (long)blockIdx.x * 256 + threadIdx.x;
    if (row >= nrows) return;
    const float* h = H + row * 256;

    float acc[40];
#pragma unroll
    for (int c = 0; c < 40; c++) acc[c] = 0.f;

#pragma unroll 1
    for (int kc = 0; kc < 256; kc += 16) {
        float hx[16];
#pragma unroll
        for (int i = 0; i < 4; i++) {
            float4 v = *(const float4*)(h + kc + i * 4);
            hx[i * 4 + 0] = v.x; hx[i * 4 + 1] = v.y;
            hx[i * 4 + 2] = v.z; hx[i * 4 + 3] = v.w;
        }
#pragma unroll
        for (int k = 0; k < 16; k++) {
            float x = hx[k];
            const float4* wr = (const float4*)&sW[(kc + k) * 40];
#pragma unroll
            for (int j = 0; j < 10; j++) {
                float4 w = wr[j];
                acc[j * 4 + 0] = fmaf(x, w.x, acc[j * 4 + 0]);
                acc[j * 4 + 1] = fmaf(x, w.y, acc[j * 4 + 1]);
                acc[j * 4 + 2] = fmaf(x, w.z, acc[j * 4 + 2]);
                acc[j * 4 + 3] = fmaf(x, w.w, acc[j * 4 + 3]);
            }
        }
    }

    float m = -1e30f;
#pragma unroll
    for (int c = 0; c < 40; c++) {
        acc[c] += sb[c];
        m = fmaxf(m, acc[c]);
    }
    float s = 0.f;
#pragma unroll
    for (int c = 0; c < 40; c++) s += __expf(acc[c] - m);
    float lse = m + __logf(s);

    float* o = out + row * 40;
#pragma unroll
    for (int j = 0; j < 10; j++) {
        float4 v = make_float4(acc[j * 4 + 0] - lse, acc[j * 4 + 1] - lse,
                               acc[j * 4 + 2] - lse, acc[j * 4 + 3] - lse);
        *(float4*)(o + j * 4) = v;
    }
}

// ---------------------------------------------------------------------------
extern "C" void kernel_launch(void* const* d_in, const int* in_sizes, int n_in,
                              void* d_out, int out_size) {
    (void)in_sizes; (void)n_in; (void)out_size;
    const float* node_x    = (const float*)d_in[0];
    const int*   nodes_map = (const int*)d_in[1];
    const int*   edges_map = (const int*)d_in[3];
    const float* W1        = (const float*)d_in[5];
    const float* b1        = (const float*)d_in[6];
    const float* W2        = (const float*)d_in[7];
    const float* b2        = (const float*)d_in[8];
    float*       out       = (float*)d_out;

    float *nodebuf, *edgebuf, *hbuf;
    cudaGetSymbolAddress((void**)&nodebuf, g_nodebuf);
    cudaGetSymbolAddress((void**)&edgebuf, g_edgebuf);
    cudaGetSymbolAddress((void**)&hbuf, g_hbuf);

    // 0) x0 -> nodebuf cols [0,128)
    copy_x_kernel<<<(N_NODES * 32 + 255) / 256, 256>>>(node_x, nodebuf);

    // 1) Layer 1 N2E: edgebuf[:,0:128] = relu(mean16(nodebuf[map, 0:128]))
    gather_mean_relu<16><<<((long)N_EDGES * 32 + 255) / 256, 256>>>(
        nodebuf, 512, nodes_map, edgebuf, 256, 0, N_EDGES, 1);

    // 2) Layer 1 E2N: nodebuf[:,128:256] = relu(mean8(edgebuf[map, 0:128]))
    gather_mean_relu<8><<<((long)N_NODES * 32 + 255) / 256, 256>>>(
        edgebuf, 256, edges_map, nodebuf, 512, 128, N_NODES, 1);

    // 3) Layer 2 N2E: edgebuf[:,0:256] = relu(mean16(nodebuf[map, 0:256]))
    gather_mean_relu<16><<<((long)N_EDGES * 2 * 32 + 255) / 256, 256>>>(
        nodebuf, 512, nodes_map, edgebuf, 256, 0, N_EDGES, 2);

    // 4) Layer 2 E2N: nodebuf[:,256:512] = relu(mean8(edgebuf[map, 0:256]))
    gather_mean_relu<8><<<((long)N_NODES * 2 * 32 + 255) / 256, 256>>>(
        edgebuf, 256, edges_map, nodebuf, 512, 256, N_NODES, 2);

    // 5) h = relu(X @ W1 + b1)
    dim3 g1(M_PAD / 128, 2);
    sgemm1_kernel<<<g1, 256>>>(nodebuf, W1, b1, hbuf);

    // 6) out = log_softmax(h @ W2 + b2)
    gemm2_lsm_kernel<<<(N_NODES + 255) / 256, 256>>>(hbuf, W2, b2, out, N_NODES);
}

// round 2
// speedup vs baseline: 1.3297x; 1.3297x over previous
#include <cuda_runtime.h>
#include <cuda_bf16.h>

// ---------------------------------------------------------------------------
// SHGNN: 2-layer hypergraph GNN + MLP head + log_softmax
// Algebraic reduction: both layers share maps/segments, so
//   final features = [x0 | nx1 | nx1 | nx2b]   (nx1 duplicated)
// with  e1  = relu(mean16(x0[nm]))
//       nx1 = relu(mean8 (e1[em]))
//       e2b = relu(mean16(nx1[nm]))
//       nx2b= relu(mean8 (e2b[em]))
// The duplicate nx1 is folded into W1:  W1e[128:256] = W1[128:256]+W1[256:384]
// => GEMM1 has K=384 only, gather steps 3/4 move half the data.
// ---------------------------------------------------------------------------

#define N_NODES 100000
#define N_EDGES 50000
#define M_PAD   100096              // 782 * 128, pad rows stay zero forever
#define KDIM    384

// Scratch (zero-initialized at module load; pad rows never written -> stay 0)
__device__ float g_nodebuf[(size_t)M_PAD * KDIM];  // [x0 | nx1 | nx2b]
__device__ float g_edgebuf[(size_t)N_EDGES * 128]; // e1, then reused for e2b
__device__ float g_hbuf[(size_t)M_PAD * 256];
__device__ float g_w1e[(size_t)KDIM * 256];

// ---------------------------------------------------------------------------
// packed f32x2 helpers (Blackwell FFMA2 path)
// ---------------------------------------------------------------------------
__device__ __forceinline__ unsigned long long pack2(float lo, float hi) {
    unsigned long long r;
    asm("mov.b64 %0, {%1, %2};" : "=l"(r) : "f"(lo), "f"(hi));
    return r;
}
__device__ __forceinline__ void fma2(unsigned long long& d,
                                     unsigned long long a, unsigned long long b) {
    asm("fma.rn.f32x2 %0, %1, %2, %0;" : "+l"(d) : "l"(a), "l"(b));
}
__device__ __forceinline__ float2 unpack2(unsigned long long v) {
    float2 r;
    asm("mov.b64 {%0, %1}, %2;" : "=f"(r.x), "=f"(r.y) : "l"(v));
    return r;
}

// ---------------------------------------------------------------------------
// Copy node_x (128 cols) into cols [0,128) of nodebuf (stride KDIM)
// ---------------------------------------------------------------------------
__global__ void copy_x_kernel(const float* __restrict__ x, float* __restrict__ nb) {
    long i = (long)blockIdx.x * blockDim.x + threadIdx.x;  // float4 index
    if (i >= (long)N_NODES * 32) return;
    long r = i >> 5;
    int  c = (int)(i & 31);
    *(float4*)(nb + r * KDIM + c * 4) = *(const float4*)(x + r * 128 + c * 4);
}

// ---------------------------------------------------------------------------
// W1e[k] = W1[k] (k<128) ; W1[k]+W1[k+128] (128<=k<256) ; W1[k+128] (k>=256)
// ---------------------------------------------------------------------------
__global__ void fold_w1_kernel(const float* __restrict__ W1, float* __restrict__ W1e) {
    int idx = blockIdx.x * blockDim.x + threadIdx.x;
    if (idx >= KDIM * 256) return;
    int k = idx >> 8;          // /256
    int n = idx & 255;
    float v;
    if (k < 128)       v = W1[k * 256 + n];
    else if (k < 256)  v = W1[k * 256 + n] + W1[(k + 128) * 256 + n];
    else               v = W1[(k + 128) * 256 + n];
    W1e[idx] = v;
}

// ---------------------------------------------------------------------------
// Contiguous-segment gather-mean-relu over 128 columns.
// One warp per segment; lane owns a float4 column slice.
// ---------------------------------------------------------------------------
template<int G>
__global__ void gather_mean_relu(const float* __restrict__ in, int in_stride, int in_off,
                                 const int* __restrict__ map,
                                 float* __restrict__ out, int out_stride, int out_off,
                                 int n_seg) {
    int seg  = (int)(((long)blockIdx.x * blockDim.x + threadIdx.x) >> 5);
    int lane = threadIdx.x & 31;
    if (seg >= n_seg) return;

    int v = 0;
    if (lane < G) v = __ldg(map + (long)seg * G + lane);

    int coloff = lane * 4;
    float4 acc = make_float4(0.f, 0.f, 0.f, 0.f);
#pragma unroll
    for (int j = 0; j < G; j++) {
        int r = __shfl_sync(0xffffffffu, v, j);
        const float4 t = *(const float4*)(in + (long)r * in_stride + in_off + coloff);
        acc.x += t.x; acc.y += t.y; acc.z += t.z; acc.w += t.w;
    }
    const float s = 1.0f / (float)G;
    float4 o;
    o.x = fmaxf(acc.x * s, 0.f);
    o.y = fmaxf(acc.y * s, 0.f);
    o.z = fmaxf(acc.z * s, 0.f);
    o.w = fmaxf(acc.w * s, 0.f);
    *(float4*)(out + (long)seg * out_stride + out_off + coloff) = o;
}

// ---------------------------------------------------------------------------
// GEMM1: H[M,256] = relu(A[M,384] @ W1e[384,256] + b1)
// 128x128x16 tiles, 256 threads, 8x8 per thread via f32x2 (rows paired).
// M padded to 100096 (pad rows of A are zero -> no bounds checks).
// ---------------------------------------------------------------------------
__global__ __launch_bounds__(256)
void sgemm1_kernel(const float* __restrict__ A, const float* __restrict__ W,
                   const float* __restrict__ bias, float* __restrict__ H) {
    __shared__ float As[16][128];   // [k][m]  (transposed)
    __shared__ float Bs[16][128];   // [k][n]

    const int tid = threadIdx.x;
    const int tr  = tid >> 4;       // 0..15  -> rows tr*8 .. tr*8+7
    const int tc  = tid & 15;       // 0..15  -> cols tc*8 .. tc*8+7
    const long rowBase = (long)blockIdx.x * 128;
    const int  colBase = blockIdx.y * 128;

    const int aRow = tid >> 2;          // 0..63
    const int aCol = (tid & 3) << 2;    // 0,4,8,12
    const int bRow = tid >> 5;          // 0..7
    const int bCol = (tid & 31) << 2;   // 0..124

    unsigned long long c2[4][8];
#pragma unroll
    for (int i = 0; i < 4; i++)
#pragma unroll
        for (int j = 0; j < 8; j++) c2[i][j] = 0ULL;

    for (int k0 = 0; k0 < KDIM; k0 += 16) {
        float4 a0 = *(const float4*)(A + (rowBase + aRow) * KDIM + k0 + aCol);
        float4 a1 = *(const float4*)(A + (rowBase + aRow + 64) * KDIM + k0 + aCol);
        float4 b0 = *(const float4*)(W + (long)(k0 + bRow) * 256 + colBase + bCol);
        float4 b1 = *(const float4*)(W + (long)(k0 + bRow + 8) * 256 + colBase + bCol);
        __syncthreads();
        As[aCol + 0][aRow] = a0.x;  As[aCol + 1][aRow] = a0.y;
        As[aCol + 2][aRow] = a0.z;  As[aCol + 3][aRow] = a0.w;
        As[aCol + 0][aRow + 64] = a1.x;  As[aCol + 1][aRow + 64] = a1.y;
        As[aCol + 2][aRow + 64] = a1.z;  As[aCol + 3][aRow + 64] = a1.w;
        *(float4*)&Bs[bRow][bCol]     = b0;
        *(float4*)&Bs[bRow + 8][bCol] = b1;
        __syncthreads();

#pragma unroll
        for (int kk = 0; kk < 16; kk++) {
            unsigned long long a2[4];
#pragma unroll
            for (int i = 0; i < 4; i++)
                a2[i] = *(const unsigned long long*)&As[kk][tr * 8 + 2 * i];
            float4 blo = *(const float4*)&Bs[kk][tc * 8];
            float4 bhi = *(const float4*)&Bs[kk][tc * 8 + 4];
            unsigned long long bb[8];
            bb[0] = pack2(blo.x, blo.x); bb[1] = pack2(blo.y, blo.y);
            bb[2] = pack2(blo.z, blo.z); bb[3] = pack2(blo.w, blo.w);
            bb[4] = pack2(bhi.x, bhi.x); bb[5] = pack2(bhi.y, bhi.y);
            bb[6] = pack2(bhi.z, bhi.z); bb[7] = pack2(bhi.w, bhi.w);
#pragma unroll
            for (int i = 0; i < 4; i++)
#pragma unroll
                for (int j = 0; j < 8; j++)
                    fma2(c2[i][j], a2[i], bb[j]);
        }
    }

    float bcol[8];
#pragma unroll
    for (int j = 0; j < 8; j++) bcol[j] = bias[colBase + tc * 8 + j];

#pragma unroll
    for (int i = 0; i < 4; i++) {
        float lo[8], hi[8];
#pragma unroll
        for (int j = 0; j < 8; j++) {
            float2 f = unpack2(c2[i][j]);
            lo[j] = fmaxf(f.x + bcol[j], 0.f);
            hi[j] = fmaxf(f.y + bcol[j], 0.f);
        }
        long r0 = rowBase + tr * 8 + 2 * i;
        float4* p0 = (float4*)(H + r0 * 256 + colBase + tc * 8);
        p0[0] = make_float4(lo[0], lo[1], lo[2], lo[3]);
        p0[1] = make_float4(lo[4], lo[5], lo[6], lo[7]);
        float4* p1 = (float4*)(H + (r0 + 1) * 256 + colBase + tc * 8);
        p1[0] = make_float4(hi[0], hi[1], hi[2], hi[3]);
        p1[1] = make_float4(hi[4], hi[5], hi[6], hi[7]);
    }
}

// ---------------------------------------------------------------------------
// GEMM2 + log_softmax: out[row,0:40] = logsoftmax(H[row,:]@W2 + b2)
// Thread-per-row, W2 in smem (broadcast LDS), 40 accumulators in regs.
// ---------------------------------------------------------------------------
__global__ __launch_bounds__(256)
void gemm2_lsm_kernel(const float* __restrict__ H, const float* __restrict__ W2,
                      const float* __restrict__ b2, float* __restrict__ out,
                      int nrows) {
    __shared__ float sW[256 * 40];
    __shared__ float sb[40];
    for (int i = threadIdx.x; i < 256 * 40; i += 256) sW[i] = W2[i];
    if (threadIdx.x < 40) sb[threadIdx.x] = b2[threadIdx.x];
    __syncthreads();

    long row = (long)blockIdx.x * 256 + threadIdx.x;
    if (row >= nrows) return;
    const float* h = H + row * 256;

    float acc[40];
#pragma unroll
    for (int c = 0; c < 40; c++) acc[c] = 0.f;

#pragma unroll 1
    for (int kc = 0; kc < 256; kc += 16) {
        float hx[16];
#pragma unroll
        for (int i = 0; i < 4; i++) {
            float4 v = *(const float4*)(h + kc + i * 4);
            hx[i * 4 + 0] = v.x; hx[i * 4 + 1] = v.y;
            hx[i * 4 + 2] = v.z; hx[i * 4 + 3] = v.w;
        }
#pragma unroll
        for (int k = 0; k < 16; k++) {
            float x = hx[k];
            const float4* wr = (const float4*)&sW[(kc + k) * 40];
#pragma unroll
            for (int j = 0; j < 10; j++) {
                float4 w = wr[j];
                acc[j * 4 + 0] = fmaf(x, w.x, acc[j * 4 + 0]);
                acc[j * 4 + 1] = fmaf(x, w.y, acc[j * 4 + 1]);
                acc[j * 4 + 2] = fmaf(x, w.z, acc[j * 4 + 2]);
                acc[j * 4 + 3] = fmaf(x, w.w, acc[j * 4 + 3]);
            }
        }
    }

    float m = -1e30f;
#pragma unroll
    for (int c = 0; c < 40; c++) {
        acc[c] += sb[c];
        m = fmaxf(m, acc[c]);
    }
    float s = 0.f;
#pragma unroll
    for (int c = 0; c < 40; c++) s += __expf(acc[c] - m);
    float lse = m + __logf(s);

    float* o = out + row * 40;
#pragma unroll
    for (int j = 0; j < 10; j++) {
        float4 v = make_float4(acc[j * 4 + 0] - lse, acc[j * 4 + 1] - lse,
                               acc[j * 4 + 2] - lse, acc[j * 4 + 3] - lse);
        *(float4*)(o + j * 4) = v;
    }
}

// ---------------------------------------------------------------------------
extern "C" void kernel_launch(void* const* d_in, const int* in_sizes, int n_in,
                              void* d_out, int out_size) {
    (void)in_sizes; (void)n_in; (void)out_size;
    const float* node_x    = (const float*)d_in[0];
    const int*   nodes_map = (const int*)d_in[1];
    const int*   edges_map = (const int*)d_in[3];
    const float* W1        = (const float*)d_in[5];
    const float* b1        = (const float*)d_in[6];
    const float* W2        = (const float*)d_in[7];
    const float* b2        = (const float*)d_in[8];
    float*       out       = (float*)d_out;

    float *nodebuf, *edgebuf, *hbuf, *w1e;
    cudaGetSymbolAddress((void**)&nodebuf, g_nodebuf);
    cudaGetSymbolAddress((void**)&edgebuf, g_edgebuf);
    cudaGetSymbolAddress((void**)&hbuf, g_hbuf);
    cudaGetSymbolAddress((void**)&w1e, g_w1e);

    // 0) x0 -> nodebuf cols [0,128);  W1e fold
    copy_x_kernel<<<(N_NODES * 32 + 255) / 256, 256>>>(node_x, nodebuf);
    fold_w1_kernel<<<(KDIM * 256 + 255) / 256, 256>>>(W1, w1e);

    // 1) e1 = relu(mean16(x0[nm]))           : nodebuf[:,0:128]  -> edgebuf
    gather_mean_relu<16><<<((long)N_EDGES * 32 + 255) / 256, 256>>>(
        nodebuf, KDIM, 0, nodes_map, edgebuf, 128, 0, N_EDGES);

    // 2) nx1 = relu(mean8(e1[em]))           : edgebuf -> nodebuf[:,128:256]
    gather_mean_relu<8><<<((long)N_NODES * 32 + 255) / 256, 256>>>(
        edgebuf, 128, 0, edges_map, nodebuf, KDIM, 128, N_NODES);

    // 3) e2b = relu(mean16(nx1[nm]))         : nodebuf[:,128:256] -> edgebuf (reuse)
    gather_mean_relu<16><<<((long)N_EDGES * 32 + 255) / 256, 256>>>(
        nodebuf, KDIM, 128, nodes_map, edgebuf, 128, 0, N_EDGES);

    // 4) nx2b = relu(mean8(e2b[em]))         : edgebuf -> nodebuf[:,256:384]
    gather_mean_relu<8><<<((long)N_NODES * 32 + 255) / 256, 256>>>(
        edgebuf, 128, 0, edges_map, nodebuf, KDIM, 256, N_NODES);

    // 5) h = relu(X(384) @ W1e + b1)
    dim3 g1(M_PAD / 128, 2);
    sgemm1_kernel<<<g1, 256>>>(nodebuf, w1e, b1, hbuf);

    // 6) out = log_softmax(h @ W2 + b2)
    gemm2_lsm_kernel<<<(N_NODES + 255) / 256, 256>>>(hbuf, W2, b2, out, N_NODES);
}

// round 4
// speedup vs baseline: 2.2613x; 1.7006x over previous
#include <cuda_runtime.h>
#include <cuda_bf16.h>
#include <stdint.h>

// ---------------------------------------------------------------------------
// SHGNN: gathers (fp32) -> bf16-split mma.sync GEMM fused with MLP head.
// tcgen05 is NOT available (harness compiles via compute_103 PTX target), so
// the tensor path is sm_80-class mma.sync.m16n8k16.bf16 (fallback HMMA pipe).
//
// Algebra (validated R2): final feat = [x0 | nx1 | nx1 | nx2b]; dup nx1 folded
// into W1 -> effective K = 384.
// GEMM1 via bf16 split: D ~= Ahi*Whi + Ahi*Wlo + Alo*Whi  (err ~2^-18)
// Head fused: h = relu(D + b1); out = log_softmax(h @ W2 + b2), H stays in smem.
// ---------------------------------------------------------------------------

#define N_NODES 100000
#define N_EDGES 50000
#define M_PAD   100096          // 782*128; pad rows stay zero
#define KD      384

__device__ float          g_edge[(size_t)N_EDGES * 128];
__device__ float          g_nx1 [(size_t)N_NODES * 128];
__device__ __nv_bfloat16  g_Ahi [(size_t)M_PAD * KD];
__device__ __nv_bfloat16  g_Alo [(size_t)M_PAD * KD];
__device__ __nv_bfloat16  g_Bhi [(size_t)256 * KD];   // [n][k]
__device__ __nv_bfloat16  g_Blo [(size_t)256 * KD];

// ---------------------------------------------------------------------------
__device__ __forceinline__ uint32_t smem_to_u32(const void* p) {
    uint32_t a;
    asm("{ .reg .u64 t; cvta.to.shared.u64 t, %1; cvt.u32.u64 %0, t; }"
        : "=r"(a) : "l"(p));
    return a;
}
__device__ __forceinline__ uint32_t sw128(uint32_t off) {
    return off ^ ((off >> 3) & 0x70);
}
#define CP_ASYNC16(dst, src) \
    asm volatile("cp.async.cg.shared.global [%0], [%1], 16;" \
        :: "r"(dst), "l"(src) : "memory")
#define CP_COMMIT() asm volatile("cp.async.commit_group;" ::: "memory")
#define CP_WAIT0()  asm volatile("cp.async.wait_group 0;" ::: "memory")

__device__ __forceinline__ void ldsm_x4(unsigned& r0, unsigned& r1,
                                        unsigned& r2, unsigned& r3, uint32_t a) {
    asm volatile("ldmatrix.sync.aligned.m8n8.x4.shared.b16 {%0,%1,%2,%3}, [%4];"
        : "=r"(r0), "=r"(r1), "=r"(r2), "=r"(r3) : "r"(a));
}
__device__ __forceinline__ void mma16816(float* c, const unsigned* a,
                                         const unsigned* b) {
    asm volatile(
        "mma.sync.aligned.m16n8k16.row.col.f32.bf16.bf16.f32 "
        "{%0,%1,%2,%3}, {%4,%5,%6,%7}, {%8,%9}, {%0,%1,%2,%3};"
        : "+f"(c[0]), "+f"(c[1]), "+f"(c[2]), "+f"(c[3])
        : "r"(a[0]), "r"(a[1]), "r"(a[2]), "r"(a[3]), "r"(b[0]), "r"(b[1]));
}

// packed f32x2
__device__ __forceinline__ void fma2(unsigned long long& d,
                                     unsigned long long a, unsigned long long b) {
    asm("fma.rn.f32x2 %0, %1, %2, %0;" : "+l"(d) : "l"(a), "l"(b));
}
__device__ __forceinline__ float2 unpack2(unsigned long long v) {
    float2 r;
    asm("mov.b64 {%0, %1}, %2;" : "=f"(r.x), "=f"(r.y) : "l"(v));
    return r;
}

// bf16 split helpers
__device__ __forceinline__ unsigned pack_bf2(float a, float b) {
    __nv_bfloat162 t = __floats2bfloat162_rn(a, b);
    return *reinterpret_cast<unsigned*>(&t);
}
__device__ __forceinline__ void split4(float4 v, uint2& hi4, uint2& lo4) {
    __nv_bfloat16 hx = __float2bfloat16_rn(v.x);
    __nv_bfloat16 hy = __float2bfloat16_rn(v.y);
    __nv_bfloat16 hz = __float2bfloat16_rn(v.z);
    __nv_bfloat16 hw = __float2bfloat16_rn(v.w);
    hi4.x = pack_bf2(v.x, v.y);
    hi4.y = pack_bf2(v.z, v.w);
    lo4.x = pack_bf2(v.x - __bfloat162float(hx), v.y - __bfloat162float(hy));
    lo4.y = pack_bf2(v.z - __bfloat162float(hz), v.w - __bfloat162float(hw));
}

// ---------------------------------------------------------------------------
// x0 -> Ahi/Alo cols [0,128)
// ---------------------------------------------------------------------------
__global__ void cvt_x_kernel(const float* __restrict__ x,
                             __nv_bfloat16* __restrict__ hi,
                             __nv_bfloat16* __restrict__ lo) {
    long i = (long)blockIdx.x * blockDim.x + threadIdx.x;
    if (i >= (long)N_NODES * 32) return;
    long r = i >> 5;
    int  c = (int)(i & 31) * 4;
    float4 v = *(const float4*)(x + r * 128 + c);
    uint2 h4, l4;
    split4(v, h4, l4);
    *(uint2*)(hi + r * KD + c) = h4;
    *(uint2*)(lo + r * KD + c) = l4;
}

// ---------------------------------------------------------------------------
// Fold W1 (512->384 rows) + transpose + bf16 split: B[n][k]
// ---------------------------------------------------------------------------
__global__ void prep_w1_kernel(const float* __restrict__ W1,
                               __nv_bfloat16* __restrict__ Bhi,
                               __nv_bfloat16* __restrict__ Blo) {
    int idx = blockIdx.x * blockDim.x + threadIdx.x;
    if (idx >= KD * 256) return;
    int k = idx >> 8;
    int n = idx & 255;
    float v;
    if (k < 128)      v = W1[k * 256 + n];
    else if (k < 256) v = W1[k * 256 + n] + W1[(k + 128) * 256 + n];
    else              v = W1[(k + 128) * 256 + n];
    __nv_bfloat16 h = __float2bfloat16_rn(v);
    Bhi[(long)n * KD + k] = h;
    Blo[(long)n * KD + k] = __float2bfloat16_rn(v - __bfloat162float(h));
}

// ---------------------------------------------------------------------------
// Contiguous-segment gather-mean-relu over 128 cols. One warp per segment.
// Optional fp32 output (stride 128) and/or bf16 hi/lo output (stride KD).
// ---------------------------------------------------------------------------
template<int G>
__global__ void gather_mean_relu(const float* __restrict__ in,
                                 const int* __restrict__ map,
                                 float* __restrict__ outf,
                                 __nv_bfloat16* __restrict__ hi,
                                 __nv_bfloat16* __restrict__ lo,
                                 int bf_off, int n_seg) {
    int seg  = (int)(((long)blockIdx.x * blockDim.x + threadIdx.x) >> 5);
    int lane = threadIdx.x & 31;
    if (seg >= n_seg) return;

    int v = 0;
    if (lane < G) v = __ldg(map + (long)seg * G + lane);

    int coloff = lane * 4;
    float4 acc = make_float4(0.f, 0.f, 0.f, 0.f);
#pragma unroll
    for (int j = 0; j < G; j++) {
        int r = __shfl_sync(0xffffffffu, v, j);
        const float4 t = *(const float4*)(in + (long)r * 128 + coloff);
        acc.x += t.x; acc.y += t.y; acc.z += t.z; acc.w += t.w;
    }
    const float s = 1.0f / (float)G;
    float4 o;
    o.x = fmaxf(acc.x * s, 0.f);
    o.y = fmaxf(acc.y * s, 0.f);
    o.z = fmaxf(acc.z * s, 0.f);
    o.w = fmaxf(acc.w * s, 0.f);
    if (outf)
        *(float4*)(outf + (long)seg * 128 + coloff) = o;
    if (hi) {
        uint2 h4, l4;
        split4(o, h4, l4);
        *(uint2*)(hi + (long)seg * KD + bf_off + coloff) = h4;
        *(uint2*)(lo + (long)seg * KD + bf_off + coloff) = l4;
    }
}

// ---------------------------------------------------------------------------
// Fused mma.sync GEMM + head.
// smem (dyn, base 1024-aligned at A0):
//   [0,32768)          A chunk double buffer (2 x 128rows x 128B)
//   [32768,98304)      B chunk double buffer (2 x 256rows x 128B)
//   union with:
//   [0,131584)         H tile 128 x 257 f32
//   [131584,152064)    Hp partial 128 x 40 f32
//   [152064,193024)    W2 256x40 f32
//   [193024,194048)    b1
//   [194048,194304)    b2
// ---------------------------------------------------------------------------
#define CH_A 16384
#define CH_B 32768
#define OFF_W2 152064
#define OFF_B1 (OFF_W2 + 40960)
#define OFF_B2 (OFF_B1 + 1024)
#define SMEM_DYN (1024 + OFF_B2 + 256)
#define HSTR 257

__global__ __launch_bounds__(256, 1)
void mma_head_kernel(const __nv_bfloat16* __restrict__ Ahi,
                     const __nv_bfloat16* __restrict__ Alo,
                     const __nv_bfloat16* __restrict__ Bhi,
                     const __nv_bfloat16* __restrict__ Blo,
                     const float* __restrict__ b1,
                     const float* __restrict__ W2,
                     const float* __restrict__ b2,
                     float* __restrict__ out) {
    extern __shared__ char smem[];
    const uint32_t sb = smem_to_u32(smem);
    const uint32_t A0u = (sb + 1023) & ~1023u;
    char* A0p = smem + (A0u - sb);
    const int tid  = threadIdx.x;
    const int wid  = tid >> 5;
    const int lane = tid & 31;
    const int warp_m = wid >> 2;      // 0..1
    const int warp_n = wid & 3;       // 0..3
    const long rowBase = (long)blockIdx.x * 128;

    float* sW2 = (float*)(A0p + OFF_W2);
    float* sb1 = (float*)(A0p + OFF_B1);
    float* sb2 = (float*)(A0p + OFF_B2);
    {
        const float4* src = (const float4*)W2;
        float4* dst = (float4*)sW2;
#pragma unroll
        for (int i = 0; i < 10; i++) dst[i * 256 + tid] = src[i * 256 + tid];
        sb1[tid] = b1[tid];
        if (tid < 40) sb2[tid] = b2[tid];
    }

    // per-thread cp.async smem targets (swizzled), computed once
    uint32_t a_dst[4], b_dst[8];
    int a_row[4], a_cu[4], b_row[8], b_cu[8];
#pragma unroll
    for (int i = 0; i < 4; i++) {
        int u = i * 256 + tid;
        a_row[i] = u >> 3; a_cu[i] = u & 7;
        a_dst[i] = sw128((uint32_t)(a_row[i] * 128 + a_cu[i] * 16));
    }
#pragma unroll
    for (int i = 0; i < 8; i++) {
        int u = i * 256 + tid;
        b_row[i] = u >> 3; b_cu[i] = u & 7;
        b_dst[i] = sw128((uint32_t)(b_row[i] * 128 + b_cu[i] * 16));
    }

    // ldmatrix per-thread base offsets (pre-swizzle)
    const uint32_t aoff_base =
        (uint32_t)((warp_m * 64 + (lane & 15)) * 128 + (lane >> 4) * 16);
    const uint32_t boff_base =
        (uint32_t)((warp_n * 64 + (lane & 7) + ((lane >> 4) << 3)) * 128 +
                   ((lane >> 3) & 1) * 16);

    float acc[4][8][4];
#pragma unroll
    for (int mt = 0; mt < 4; mt++)
#pragma unroll
        for (int nt = 0; nt < 8; nt++)
#pragma unroll
            for (int q = 0; q < 4; q++) acc[mt][nt][q] = 0.f;

    // issue chunk 0
    {
        const uint4* asrc = (const uint4*)(Ahi + rowBase * KD);
        const uint4* bsrc = (const uint4*)Bhi;
#pragma unroll
        for (int i = 0; i < 4; i++)
            CP_ASYNC16(A0u + a_dst[i], asrc + a_row[i] * 48 + a_cu[i]);
#pragma unroll
        for (int i = 0; i < 8; i++)
            CP_ASYNC16(A0u + CH_A * 2 + b_dst[i], bsrc + b_row[i] * 48 + b_cu[i]);
        CP_COMMIT();
    }

#pragma unroll 1
    for (int s = 0; s < 18; s++) {
        CP_WAIT0();
        __syncthreads();
        if (s < 17) {
            const int s1 = s + 1;
            const int pass = s1 / 6;
            const int kc = s1 - pass * 6;
            const int buf = s1 & 1;
            const __nv_bfloat16* Asel = (pass < 2) ? Ahi : Alo;
            const __nv_bfloat16* Bsel = (pass == 1) ? Blo : Bhi;
            const uint4* asrc = (const uint4*)(Asel + rowBase * KD + kc * 64);
            const uint4* bsrc = (const uint4*)(Bsel + kc * 64);
            uint32_t ab = A0u + buf * CH_A;
            uint32_t bb = A0u + CH_A * 2 + buf * CH_B;
#pragma unroll
            for (int i = 0; i < 4; i++)
                CP_ASYNC16(ab + a_dst[i], asrc + a_row[i] * 48 + a_cu[i]);
#pragma unroll
            for (int i = 0; i < 8; i++)
                CP_ASYNC16(bb + b_dst[i], bsrc + b_row[i] * 48 + b_cu[i]);
            CP_COMMIT();
        }
        // compute on buf s&1
        const uint32_t abase = A0u + (s & 1) * CH_A;
        const uint32_t bbase = A0u + CH_A * 2 + (s & 1) * CH_B;
#pragma unroll
        for (int kk = 0; kk < 4; kk++) {
            unsigned af[4][4];
#pragma unroll
            for (int mt = 0; mt < 4; mt++)
                ldsm_x4(af[mt][0], af[mt][1], af[mt][2], af[mt][3],
                        abase + sw128(aoff_base + (uint32_t)(mt * 2048 + kk * 32)));
#pragma unroll
            for (int ntp = 0; ntp < 4; ntp++) {
                unsigned bf[4];
                ldsm_x4(bf[0], bf[1], bf[2], bf[3],
                        bbase + sw128(boff_base + (uint32_t)(ntp * 2048 + kk * 32)));
#pragma unroll
                for (int mt = 0; mt < 4; mt++) {
                    mma16816(acc[mt][2 * ntp],     af[mt], bf);
                    mma16816(acc[mt][2 * ntp + 1], af[mt], bf + 2);
                }
            }
        }
    }

    // ---- epilogue: acc -> smem H (union over A/B buffers) ----
    __syncthreads();
    float* Hs = (float*)A0p;
    {
        int qr = lane >> 2;
        int qc = (lane & 3) * 2;
#pragma unroll
        for (int mt = 0; mt < 4; mt++) {
            int r0 = warp_m * 64 + mt * 16 + qr;
#pragma unroll
            for (int nt = 0; nt < 8; nt++) {
                int c = warp_n * 64 + nt * 8 + qc;
                Hs[r0 * HSTR + c]           = acc[mt][nt][0];
                Hs[r0 * HSTR + c + 1]       = acc[mt][nt][1];
                Hs[(r0 + 8) * HSTR + c]     = acc[mt][nt][2];
                Hs[(r0 + 8) * HSTR + c + 1] = acc[mt][nt][3];
            }
        }
    }
    __syncthreads();

    // ---- head: relu(H+b1) @ W2, split-K over 2 halves ----
    const int row  = tid & 127;
    const int half = tid >> 7;
    const float* hrow = Hs + row * HSTR + half * 128;
    const float* b1h  = sb1 + half * 128;
    unsigned long long a2[20];
#pragma unroll
    for (int t = 0; t < 20; t++) a2[t] = 0ULL;
#pragma unroll 4
    for (int k = 0; k < 128; k++) {
        float h = fmaxf(hrow[k] + b1h[k], 0.f);
        unsigned long long hh;
        asm("mov.b64 %0, {%1, %1};" : "=l"(hh) : "f"(h));
        const unsigned long long* w2r =
            (const unsigned long long*)(sW2 + (half * 128 + k) * 40);
#pragma unroll
        for (int t = 0; t < 20; t++) fma2(a2[t], hh, w2r[t]);
    }
    unsigned long long* Hp = (unsigned long long*)(A0p + 128 * HSTR * 4);
    if (half == 1) {
#pragma unroll
        for (int t = 0; t < 20; t++) Hp[row * 20 + t] = a2[t];
    }
    __syncthreads();
    if (half == 0 && rowBase + row < N_NODES) {
        float v[40];
#pragma unroll
        for (int t = 0; t < 20; t++) {
            float2 f0 = unpack2(a2[t]);
            float2 f1 = unpack2(Hp[row * 20 + t]);
            v[2 * t]     = f0.x + f1.x + sb2[2 * t];
            v[2 * t + 1] = f0.y + f1.y + sb2[2 * t + 1];
        }
        float m = -1e30f;
#pragma unroll
        for (int c = 0; c < 40; c++) m = fmaxf(m, v[c]);
        float ssum = 0.f;
#pragma unroll
        for (int c = 0; c < 40; c++) ssum += __expf(v[c] - m);
        float lse = m + __logf(ssum);
        float* o = out + (rowBase + row) * 40;
#pragma unroll
        for (int j = 0; j < 10; j++)
            *(float4*)(o + j * 4) = make_float4(v[4 * j] - lse, v[4 * j + 1] - lse,
                                                v[4 * j + 2] - lse, v[4 * j + 3] - lse);
    }
}

// ---------------------------------------------------------------------------
extern "C" void kernel_launch(void* const* d_in, const int* in_sizes, int n_in,
                              void* d_out, int out_size) {
    (void)in_sizes; (void)n_in; (void)out_size;
    const float* node_x    = (const float*)d_in[0];
    const int*   nodes_map = (const int*)d_in[1];
    const int*   edges_map = (const int*)d_in[3];
    const float* W1        = (const float*)d_in[5];
    const float* b1        = (const float*)d_in[6];
    const float* W2        = (const float*)d_in[7];
    const float* b2        = (const float*)d_in[8];
    float*       out       = (float*)d_out;

    float *edgebuf, *nx1;
    __nv_bfloat16 *Ahi, *Alo, *Bhi, *Blo;
    cudaGetSymbolAddress((void**)&edgebuf, g_edge);
    cudaGetSymbolAddress((void**)&nx1, g_nx1);
    cudaGetSymbolAddress((void**)&Ahi, g_Ahi);
    cudaGetSymbolAddress((void**)&Alo, g_Alo);
    cudaGetSymbolAddress((void**)&Bhi, g_Bhi);
    cudaGetSymbolAddress((void**)&Blo, g_Blo);

    cudaFuncSetAttribute(mma_head_kernel,
                         cudaFuncAttributeMaxDynamicSharedMemorySize, SMEM_DYN);

    // 0) x0 -> Ahi/Alo[:,0:128];  W1 fold -> Bhi/Blo
    cvt_x_kernel<<<(N_NODES * 32 + 255) / 256, 256>>>(node_x, Ahi, Alo);
    prep_w1_kernel<<<(KD * 256 + 255) / 256, 256>>>(W1, Bhi, Blo);

    // 1) e1 = relu(mean16(x0[nm]))
    gather_mean_relu<16><<<((long)N_EDGES * 32 + 255) / 256, 256>>>(
        node_x, nodes_map, edgebuf, (__nv_bfloat16*)nullptr, (__nv_bfloat16*)nullptr,
        0, N_EDGES);
    // 2) nx1 = relu(mean8(e1[em]))  -> fp32 nx1 + Ahi/Alo[:,128:256]
    gather_mean_relu<8><<<((long)N_NODES * 32 + 255) / 256, 256>>>(
        edgebuf, edges_map, nx1, Ahi, Alo, 128, N_NODES);
    // 3) e2b = relu(mean16(nx1[nm]))
    gather_mean_relu<16><<<((long)N_EDGES * 32 + 255) / 256, 256>>>(
        nx1, nodes_map, edgebuf, (__nv_bfloat16*)nullptr, (__nv_bfloat16*)nullptr,
        0, N_EDGES);
    // 4) nx2b -> Ahi/Alo[:,256:384] only
    gather_mean_relu<8><<<((long)N_NODES * 32 + 255) / 256, 256>>>(
        edgebuf, edges_map, (float*)nullptr, Ahi, Alo, 256, N_NODES);

    // 5) fused mma.sync GEMM + head
    mma_head_kernel<<<M_PAD / 128, 256, SMEM_DYN>>>(Ahi, Alo, Bhi, Blo,
                                                    b1, W2, b2, out);
}

// round 7
// speedup vs baseline: 2.5747x; 1.1386x over previous
#include <cuda_runtime.h>
#include <cuda_bf16.h>
#include <stdint.h>

// ---------------------------------------------------------------------------
// SHGNN: multi-segment gathers (fp32) -> 2-pass bf16-split mma.sync GEMM
// fused with MLP head (relu+b1, W2, b2, log_softmax; H never leaves smem).
//
// D ~= Ahi@Bhi + Alo@Bhi = A@Bhi (A at ~16-bit mantissa); only W1's bf16
// rounding remains, and log_softmax cancels most of it (validated R4:
// 3-pass measured 9.5e-8 vs 2e-6 theory => ~20x cancellation).
// ---------------------------------------------------------------------------

#define N_NODES 100000
#define N_EDGES 50000
#define M_PAD   100096          // 782*128; pad rows stay zero
#define KD      384

__device__ float          g_edge[(size_t)N_EDGES * 128];
__device__ float          g_nx1 [(size_t)N_NODES * 128];
__device__ __nv_bfloat16  g_Ahi [(size_t)M_PAD * KD];
__device__ __nv_bfloat16  g_Alo [(size_t)M_PAD * KD];
__device__ __nv_bfloat16  g_Bhi [(size_t)256 * KD];   // [n][k]

// ---------------------------------------------------------------------------
__device__ __forceinline__ uint32_t smem_to_u32(const void* p) {
    uint32_t a;
    asm("{ .reg .u64 t; cvta.to.shared.u64 t, %1; cvt.u32.u64 %0, t; }"
        : "=r"(a) : "l"(p));
    return a;
}
__device__ __forceinline__ uint32_t sw128(uint32_t off) {
    return off ^ ((off >> 3) & 0x70);
}
#define CP_ASYNC16(dst, src) \
    asm volatile("cp.async.cg.shared.global [%0], [%1], 16;" \
        :: "r"(dst), "l"(src) : "memory")
#define CP_COMMIT() asm volatile("cp.async.commit_group;" ::: "memory")
#define CP_WAIT0()  asm volatile("cp.async.wait_group 0;" ::: "memory")

__device__ __forceinline__ void ldsm_x4(unsigned& r0, unsigned& r1,
                                        unsigned& r2, unsigned& r3, uint32_t a) {
    asm volatile("ldmatrix.sync.aligned.m8n8.x4.shared.b16 {%0,%1,%2,%3}, [%4];"
        : "=r"(r0), "=r"(r1), "=r"(r2), "=r"(r3) : "r"(a));
}
__device__ __forceinline__ void mma16816(float* c, const unsigned* a,
                                         const unsigned* b) {
    asm volatile(
        "mma.sync.aligned.m16n8k16.row.col.f32.bf16.bf16.f32 "
        "{%0,%1,%2,%3}, {%4,%5,%6,%7}, {%8,%9}, {%0,%1,%2,%3};"
        : "+f"(c[0]), "+f"(c[1]), "+f"(c[2]), "+f"(c[3])
        : "r"(a[0]), "r"(a[1]), "r"(a[2]), "r"(a[3]), "r"(b[0]), "r"(b[1]));
}

// packed f32x2
__device__ __forceinline__ void fma2(unsigned long long& d,
                                     unsigned long long a, unsigned long long b) {
    asm("fma.rn.f32x2 %0, %1, %2, %0;" : "+l"(d) : "l"(a), "l"(b));
}
__device__ __forceinline__ float2 unpack2(unsigned long long v) {
    float2 r;
    asm("mov.b64 {%0, %1}, %2;" : "=f"(r.x), "=f"(r.y) : "l"(v));
    return r;
}

// bf16 split helpers
__device__ __forceinline__ unsigned pack_bf2(float a, float b) {
    __nv_bfloat162 t = __floats2bfloat162_rn(a, b);
    return *reinterpret_cast<unsigned*>(&t);
}
__device__ __forceinline__ void split4(float4 v, uint2& hi4, uint2& lo4) {
    __nv_bfloat16 hx = __float2bfloat16_rn(v.x);
    __nv_bfloat16 hy = __float2bfloat16_rn(v.y);
    __nv_bfloat16 hz = __float2bfloat16_rn(v.z);
    __nv_bfloat16 hw = __float2bfloat16_rn(v.w);
    hi4.x = pack_bf2(v.x, v.y);
    hi4.y = pack_bf2(v.z, v.w);
    lo4.x = pack_bf2(v.x - __bfloat162float(hx), v.y - __bfloat162float(hy));
    lo4.y = pack_bf2(v.z - __bfloat162float(hz), v.w - __bfloat162float(hw));
}

// ---------------------------------------------------------------------------
// x0 -> Ahi/Alo cols [0,128)
// ---------------------------------------------------------------------------
__global__ void cvt_x_kernel(const float* __restrict__ x,
                             __nv_bfloat16* __restrict__ hi,
                             __nv_bfloat16* __restrict__ lo) {
    long i = (long)blockIdx.x * blockDim.x + threadIdx.x;
    if (i >= (long)N_NODES * 32) return;
    long r = i >> 5;
    int  c = (int)(i & 31) * 4;
    float4 v = *(const float4*)(x + r * 128 + c);
    uint2 h4, l4;
    split4(v, h4, l4);
    *(uint2*)(hi + r * KD + c) = h4;
    *(uint2*)(lo + r * KD + c) = l4;
}

// ---------------------------------------------------------------------------
// Fold W1 (512->384 rows) + transpose + bf16: Bhi[n][k]
// ---------------------------------------------------------------------------
__global__ void prep_w1_kernel(const float* __restrict__ W1,
                               __nv_bfloat16* __restrict__ Bhi) {
    int idx = blockIdx.x * blockDim.x + threadIdx.x;
    if (idx >= KD * 256) return;
    int k = idx >> 8;
    int n = idx & 255;
    float v;
    if (k < 128)      v = W1[k * 256 + n];
    else if (k < 256) v = W1[k * 256 + n] + W1[(k + 128) * 256 + n];
    else              v = W1[(k + 128) * 256 + n];
    Bhi[(long)n * KD + k] = __float2bfloat16_rn(v);
}

// ---------------------------------------------------------------------------
// Contiguous-segment gather-mean-relu over 128 cols.
// One warp handles S segments concurrently (S*G == 32 lanes of indices),
// interleaving S independent 512B row loads per j-step for MLP.
// ---------------------------------------------------------------------------
template<int G, int S>
__global__ void gather_mean_relu(const float* __restrict__ in,
                                 const int* __restrict__ map,
                                 float* __restrict__ outf,
                                 __nv_bfloat16* __restrict__ hi,
                                 __nv_bfloat16* __restrict__ lo,
                                 int bf_off, int n_seg) {
    int gw   = (int)(((long)blockIdx.x * blockDim.x + threadIdx.x) >> 5);
    int lane = threadIdx.x & 31;
    int segBase = gw * S;
    if (segBase >= n_seg) return;

    // 32 lanes hold S*G indices (S*G == 32)
    int v = __ldg(map + (long)segBase * G + lane);

    const int coloff = lane * 4;
    float4 acc[S];
#pragma unroll
    for (int s = 0; s < S; s++) acc[s] = make_float4(0.f, 0.f, 0.f, 0.f);

#pragma unroll
    for (int j = 0; j < G; j++) {
#pragma unroll
        for (int s = 0; s < S; s++) {
            int r = __shfl_sync(0xffffffffu, v, s * G + j);
            const float4 t = *(const float4*)(in + (long)r * 128 + coloff);
            acc[s].x += t.x; acc[s].y += t.y; acc[s].z += t.z; acc[s].w += t.w;
        }
    }
    const float sc = 1.0f / (float)G;
#pragma unroll
    for (int s = 0; s < S; s++) {
        float4 o;
        o.x = fmaxf(acc[s].x * sc, 0.f);
        o.y = fmaxf(acc[s].y * sc, 0.f);
        o.z = fmaxf(acc[s].z * sc, 0.f);
        o.w = fmaxf(acc[s].w * sc, 0.f);
        long seg = segBase + s;
        if (outf)
            *(float4*)(outf + seg * 128 + coloff) = o;
        if (hi) {
            uint2 h4, l4;
            split4(o, h4, l4);
            *(uint2*)(hi + seg * KD + bf_off + coloff) = h4;
            *(uint2*)(lo + seg * KD + bf_off + coloff) = l4;
        }
    }
}

// ---------------------------------------------------------------------------
// Fused mma.sync GEMM (2 passes x 6 K-chunks) + head.
// smem (dyn, base 1024-aligned at A0):
//   [0,32768)          A chunk double buffer (2 x 128rows x 128B)
//   [32768,98304)      B chunk double buffer (2 x 256rows x 128B)
//   union with  H tile 128x257 f32 [0,131584) + Hp partial [131584,152064)
//   [152064,193024)    W2 256x40 f32;  then b1 (1KB), b2 (256B)
// ---------------------------------------------------------------------------
#define CH_A 16384
#define CH_B 32768
#define OFF_W2 152064
#define OFF_B1 (OFF_W2 + 40960)
#define OFF_B2 (OFF_B1 + 1024)
#define SMEM_DYN (1024 + OFF_B2 + 256)
#define HSTR 257
#define NCHUNK 12

__global__ __launch_bounds__(256, 1)
void mma_head_kernel(const __nv_bfloat16* __restrict__ Ahi,
                     const __nv_bfloat16* __restrict__ Alo,
                     const __nv_bfloat16* __restrict__ Bhi,
                     const float* __restrict__ b1,
                     const float* __restrict__ W2,
                     const float* __restrict__ b2,
                     float* __restrict__ out) {
    extern __shared__ char smem[];
    const uint32_t sb = smem_to_u32(smem);
    const uint32_t A0u = (sb + 1023) & ~1023u;
    char* A0p = smem + (A0u - sb);
    const int tid  = threadIdx.x;
    const int wid  = tid >> 5;
    const int lane = tid & 31;
    const int warp_m = wid >> 2;      // 0..1
    const int warp_n = wid & 3;       // 0..3
    const long rowBase = (long)blockIdx.x * 128;

    float* sW2 = (float*)(A0p + OFF_W2);
    float* sb1 = (float*)(A0p + OFF_B1);
    float* sb2 = (float*)(A0p + OFF_B2);
    {
        const float4* src = (const float4*)W2;
        float4* dst = (float4*)sW2;
#pragma unroll
        for (int i = 0; i < 10; i++) dst[i * 256 + tid] = src[i * 256 + tid];
        sb1[tid] = b1[tid];
        if (tid < 40) sb2[tid] = b2[tid];
    }

    // per-thread cp.async smem targets (swizzled), computed once
    uint32_t a_dst[4], b_dst[8];
    int a_row[4], a_cu[4], b_row[8], b_cu[8];
#pragma unroll
    for (int i = 0; i < 4; i++) {
        int u = i * 256 + tid;
        a_row[i] = u >> 3; a_cu[i] = u & 7;
        a_dst[i] = sw128((uint32_t)(a_row[i] * 128 + a_cu[i] * 16));
    }
#pragma unroll
    for (int i = 0; i < 8; i++) {
        int u = i * 256 + tid;
        b_row[i] = u >> 3; b_cu[i] = u & 7;
        b_dst[i] = sw128((uint32_t)(b_row[i] * 128 + b_cu[i] * 16));
    }

    const uint32_t aoff_base =
        (uint32_t)((warp_m * 64 + (lane & 15)) * 128 + (lane >> 4) * 16);
    const uint32_t boff_base =
        (uint32_t)((warp_n * 64 + (lane & 7) + ((lane >> 4) << 3)) * 128 +
                   ((lane >> 3) & 1) * 16);

    float acc[4][8][4];
#pragma unroll
    for (int mt = 0; mt < 4; mt++)
#pragma unroll
        for (int nt = 0; nt < 8; nt++)
#pragma unroll
            for (int q = 0; q < 4; q++) acc[mt][nt][q] = 0.f;

    // issue chunk 0
    {
        const uint4* asrc = (const uint4*)(Ahi + rowBase * KD);
        const uint4* bsrc = (const uint4*)Bhi;
#pragma unroll
        for (int i = 0; i < 4; i++)
            CP_ASYNC16(A0u + a_dst[i], asrc + a_row[i] * 48 + a_cu[i]);
#pragma unroll
        for (int i = 0; i < 8; i++)
            CP_ASYNC16(A0u + CH_A * 2 + b_dst[i], bsrc + b_row[i] * 48 + b_cu[i]);
        CP_COMMIT();
    }

#pragma unroll 1
    for (int s = 0; s < NCHUNK; s++) {
        CP_WAIT0();
        __syncthreads();
        if (s < NCHUNK - 1) {
            const int s1 = s + 1;
            const int pass = s1 / 6;
            const int kc = s1 - pass * 6;
            const int buf = s1 & 1;
            const __nv_bfloat16* Asel = (pass == 0) ? Ahi : Alo;
            const uint4* asrc = (const uint4*)(Asel + rowBase * KD + kc * 64);
            const uint4* bsrc = (const uint4*)(Bhi + kc * 64);
            uint32_t ab = A0u + buf * CH_A;
            uint32_t bb = A0u + CH_A * 2 + buf * CH_B;
#pragma unroll
            for (int i = 0; i < 4; i++)
                CP_ASYNC16(ab + a_dst[i], asrc + a_row[i] * 48 + a_cu[i]);
#pragma unroll
            for (int i = 0; i < 8; i++)
                CP_ASYNC16(bb + b_dst[i], bsrc + b_row[i] * 48 + b_cu[i]);
            CP_COMMIT();
        }
        const uint32_t abase = A0u + (s & 1) * CH_A;
        const uint32_t bbase = A0u + CH_A * 2 + (s & 1) * CH_B;
#pragma unroll
        for (int kk = 0; kk < 4; kk++) {
            unsigned af[4][4];
#pragma unroll
            for (int mt = 0; mt < 4; mt++)
                ldsm_x4(af[mt][0], af[mt][1], af[mt][2], af[mt][3],
                        abase + sw128(aoff_base + (uint32_t)(mt * 2048 + kk * 32)));
#pragma unroll
            for (int ntp = 0; ntp < 4; ntp++) {
                unsigned bf[4];
                ldsm_x4(bf[0], bf[1], bf[2], bf[3],
                        bbase + sw128(boff_base + (uint32_t)(ntp * 2048 + kk * 32)));
#pragma unroll
                for (int mt = 0; mt < 4; mt++) {
                    mma16816(acc[mt][2 * ntp],     af[mt], bf);
                    mma16816(acc[mt][2 * ntp + 1], af[mt], bf + 2);
                }
            }
        }
    }

    // ---- epilogue: acc -> smem H (union over A/B buffers) ----
    __syncthreads();
    float* Hs = (float*)A0p;
    {
        int qr = lane >> 2;
        int qc = (lane & 3) * 2;
#pragma unroll
        for (int mt = 0; mt < 4; mt++) {
            int r0 = warp_m * 64 + mt * 16 + qr;
#pragma unroll
            for (int nt = 0; nt < 8; nt++) {
                int c = warp_n * 64 + nt * 8 + qc;
                Hs[r0 * HSTR + c]           = acc[mt][nt][0];
                Hs[r0 * HSTR + c + 1]       = acc[mt][nt][1];
                Hs[(r0 + 8) * HSTR + c]     = acc[mt][nt][2];
                Hs[(r0 + 8) * HSTR + c + 1] = acc[mt][nt][3];
            }
        }
    }
    __syncthreads();

    // ---- head: relu(H+b1) @ W2, split-K over 2 halves ----
    const int row  = tid & 127;
    const int half = tid >> 7;
    const float* hrow = Hs + row * HSTR + half * 128;
    const float* b1h  = sb1 + half * 128;
    unsigned long long a2[20];
#pragma unroll
    for (int t = 0; t < 20; t++) a2[t] = 0ULL;
#pragma unroll 4
    for (int k = 0; k < 128; k++) {
        float h = fmaxf(hrow[k] + b1h[k], 0.f);
        unsigned long long hh;
        asm("mov.b64 %0, {%1, %1};" : "=l"(hh) : "f"(h));
        const unsigned long long* w2r =
            (const unsigned long long*)(sW2 + (half * 128 + k) * 40);
#pragma unroll
        for (int t = 0; t < 20; t++) fma2(a2[t], hh, w2r[t]);
    }
    unsigned long long* Hp = (unsigned long long*)(A0p + 128 * HSTR * 4);
    if (half == 1) {
#pragma unroll
        for (int t = 0; t < 20; t++) Hp[row * 20 + t] = a2[t];
    }
    __syncthreads();
    if (half == 0 && rowBase + row < N_NODES) {
        float v[40];
#pragma unroll
        for (int t = 0; t < 20; t++) {
            float2 f0 = unpack2(a2[t]);
            float2 f1 = unpack2(Hp[row * 20 + t]);
            v[2 * t]     = f0.x + f1.x + sb2[2 * t];
            v[2 * t + 1] = f0.y + f1.y + sb2[2 * t + 1];
        }
        float m = -1e30f;
#pragma unroll
        for (int c = 0; c < 40; c++) m = fmaxf(m, v[c]);
        float ssum = 0.f;
#pragma unroll
        for (int c = 0; c < 40; c++) ssum += __expf(v[c] - m);
        float lse = m + __logf(ssum);
        float* o = out + (rowBase + row) * 40;
#pragma unroll
        for (int j = 0; j < 10; j++)
            *(float4*)(o + j * 4) = make_float4(v[4 * j] - lse, v[4 * j + 1] - lse,
                                                v[4 * j + 2] - lse, v[4 * j + 3] - lse);
    }
}

// ---------------------------------------------------------------------------
extern "C" void kernel_launch(void* const* d_in, const int* in_sizes, int n_in,
                              void* d_out, int out_size) {
    (void)in_sizes; (void)n_in; (void)out_size;
    const float* node_x    = (const float*)d_in[0];
    const int*   nodes_map = (const int*)d_in[1];
    const int*   edges_map = (const int*)d_in[3];
    const float* W1        = (const float*)d_in[5];
    const float* b1        = (const float*)d_in[6];
    const float* W2        = (const float*)d_in[7];
    const float* b2        = (const float*)d_in[8];
    float*       out       = (float*)d_out;

    float *edgebuf, *nx1;
    __nv_bfloat16 *Ahi, *Alo, *Bhi;
    cudaGetSymbolAddress((void**)&edgebuf, g_edge);
    cudaGetSymbolAddress((void**)&nx1, g_nx1);
    cudaGetSymbolAddress((void**)&Ahi, g_Ahi);
    cudaGetSymbolAddress((void**)&Alo, g_Alo);
    cudaGetSymbolAddress((void**)&Bhi, g_Bhi);

    cudaFuncSetAttribute(mma_head_kernel,
                         cudaFuncAttributeMaxDynamicSharedMemorySize, SMEM_DYN);

    // 0) x0 -> Ahi/Alo[:,0:128];  W1 fold -> Bhi
    cvt_x_kernel<<<(N_NODES * 32 + 255) / 256, 256>>>(node_x, Ahi, Alo);
    prep_w1_kernel<<<(KD * 256 + 255) / 256, 256>>>(W1, Bhi);

    // warps = ceil(n_seg/S); blocks = ceil(warps*32/256)
    const int blk16 = ((N_EDGES + 1) / 2 * 32 + 255) / 256;   // G=16,S=2
    const int blk8  = ((N_NODES + 3) / 4 * 32 + 255) / 256;   // G=8, S=4

    // 1) e1 = relu(mean16(x0[nm]))
    gather_mean_relu<16, 2><<<blk16, 256>>>(
        node_x, nodes_map, edgebuf, (__nv_bfloat16*)nullptr, (__nv_bfloat16*)nullptr,
        0, N_EDGES);
    // 2) nx1 = relu(mean8(e1[em]))  -> fp32 nx1 + Ahi/Alo[:,128:256]
    gather_mean_relu<8, 4><<<blk8, 256>>>(
        edgebuf, edges_map, nx1, Ahi, Alo, 128, N_NODES);
    // 3) e2b = relu(mean16(nx1[nm]))
    gather_mean_relu<16, 2><<<blk16, 256>>>(
        nx1, nodes_map, edgebuf, (__nv_bfloat16*)nullptr, (__nv_bfloat16*)nullptr,
        0, N_EDGES);
    // 4) nx2b -> Ahi/Alo[:,256:384] only
    gather_mean_relu<8, 4><<<blk8, 256>>>(
        edgebuf, edges_map, (float*)nullptr, Ahi, Alo, 256, N_NODES);

    // 5) fused 2-pass mma.sync GEMM + head
    mma_head_kernel<<<M_PAD / 128, 256, SMEM_DYN>>>(Ahi, Alo, Bhi,
                                                    b1, W2, b2, out);
}

// round 9
// speedup vs baseline: 3.2224x; 1.2515x over previous
#include <cuda_runtime.h>
#include <cuda_bf16.h>
#include <stdint.h>

// ---------------------------------------------------------------------------
// SHGNN: gathers (fp32, one warp/segment) -> single-pass bf16 mma.sync GEMM
// fused with MLP head (relu+b1, W2, b2, log_softmax; H never leaves smem).
//
// Precision ledger (measured):
//   R4 3-pass (exact A, W1 split):  rel_err 9.5e-8
//   R7 2-pass (exact A, W1 bf16):   rel_err 2.3e-5   <- W1 rounding only
//   R8 1-pass (A bf16, W1 bf16):    predicted ~sqrt(2)*2.3e-5 ~ 3-5e-5
// log_softmax cancels common-mode error (~20x observed).
// Multi-segment gathers REVERTED: R7 measured S=4 slower than S=1 (37.2 vs
// 33.7us) - loads within the j-loop were already independent; S>1 only cut
// warp-level parallelism.
// ---------------------------------------------------------------------------

#define N_NODES 100000
#define N_EDGES 50000
#define M_PAD   100096          // 782*128; pad rows stay zero
#define KD      384

__device__ float          g_edge[(size_t)N_EDGES * 128];
__device__ float          g_nx1 [(size_t)N_NODES * 128];
__device__ __nv_bfloat16  g_A   [(size_t)M_PAD * KD];
__device__ __nv_bfloat16  g_B   [(size_t)256 * KD];   // [n][k]

// ---------------------------------------------------------------------------
__device__ __forceinline__ uint32_t smem_to_u32(const void* p) {
    uint32_t a;
    asm("{ .reg .u64 t; cvta.to.shared.u64 t, %1; cvt.u32.u64 %0, t; }"
        : "=r"(a) : "l"(p));
    return a;
}
__device__ __forceinline__ uint32_t sw128(uint32_t off) {
    return off ^ ((off >> 3) & 0x70);
}
#define CP_ASYNC16(dst, src) \
    asm volatile("cp.async.cg.shared.global [%0], [%1], 16;" \
        :: "r"(dst), "l"(src) : "memory")
#define CP_COMMIT() asm volatile("cp.async.commit_group;" ::: "memory")
#define CP_WAIT0()  asm volatile("cp.async.wait_group 0;" ::: "memory")

__device__ __forceinline__ void ldsm_x4(unsigned& r0, unsigned& r1,
                                        unsigned& r2, unsigned& r3, uint32_t a) {
    asm volatile("ldmatrix.sync.aligned.m8n8.x4.shared.b16 {%0,%1,%2,%3}, [%4];"
        : "=r"(r0), "=r"(r1), "=r"(r2), "=r"(r3) : "r"(a));
}
__device__ __forceinline__ void mma16816(float* c, const unsigned* a,
                                         const unsigned* b) {
    asm volatile(
        "mma.sync.aligned.m16n8k16.row.col.f32.bf16.bf16.f32 "
        "{%0,%1,%2,%3}, {%4,%5,%6,%7}, {%8,%9}, {%0,%1,%2,%3};"
        : "+f"(c[0]), "+f"(c[1]), "+f"(c[2]), "+f"(c[3])
        : "r"(a[0]), "r"(a[1]), "r"(a[2]), "r"(a[3]), "r"(b[0]), "r"(b[1]));
}

// packed f32x2
__device__ __forceinline__ void fma2(unsigned long long& d,
                                     unsigned long long a, unsigned long long b) {
    asm("fma.rn.f32x2 %0, %1, %2, %0;" : "+l"(d) : "l"(a), "l"(b));
}
__device__ __forceinline__ float2 unpack2(unsigned long long v) {
    float2 r;
    asm("mov.b64 {%0, %1}, %2;" : "=f"(r.x), "=f"(r.y) : "l"(v));
    return r;
}
__device__ __forceinline__ uint2 to_bf4(float4 v) {
    __nv_bfloat162 p0 = __floats2bfloat162_rn(v.x, v.y);
    __nv_bfloat162 p1 = __floats2bfloat162_rn(v.z, v.w);
    uint2 r;
    r.x = *reinterpret_cast<unsigned*>(&p0);
    r.y = *reinterpret_cast<unsigned*>(&p1);
    return r;
}

// ---------------------------------------------------------------------------
// x0 -> A cols [0,128) as bf16
// ---------------------------------------------------------------------------
__global__ void cvt_x_kernel(const float* __restrict__ x,
                             __nv_bfloat16* __restrict__ A) {
    long i = (long)blockIdx.x * blockDim.x + threadIdx.x;
    if (i >= (long)N_NODES * 32) return;
    long r = i >> 5;
    int  c = (int)(i & 31) * 4;
    float4 v = *(const float4*)(x + r * 128 + c);
    *(uint2*)(A + r * KD + c) = to_bf4(v);
}

// ---------------------------------------------------------------------------
// Fold W1 (512->384 rows) + transpose + bf16: B[n][k]
// ---------------------------------------------------------------------------
__global__ void prep_w1_kernel(const float* __restrict__ W1,
                               __nv_bfloat16* __restrict__ B) {
    int idx = blockIdx.x * blockDim.x + threadIdx.x;
    if (idx >= KD * 256) return;
    int k = idx >> 8;
    int n = idx & 255;
    float v;
    if (k < 128)      v = W1[k * 256 + n];
    else if (k < 256) v = W1[k * 256 + n] + W1[(k + 128) * 256 + n];
    else              v = W1[(k + 128) * 256 + n];
    B[(long)n * KD + k] = __float2bfloat16_rn(v);
}

// ---------------------------------------------------------------------------
// Contiguous-segment gather-mean-relu over 128 cols. One warp per segment
// (S=1: measured fastest in R4/R7). Optional fp32 out + bf16 out.
// ---------------------------------------------------------------------------
template<int G>
__global__ void gather_mean_relu(const float* __restrict__ in,
                                 const int* __restrict__ map,
                                 float* __restrict__ outf,
                                 __nv_bfloat16* __restrict__ bfout,
                                 int bf_off, int n_seg) {
    int seg  = (int)(((long)blockIdx.x * blockDim.x + threadIdx.x) >> 5);
    int lane = threadIdx.x & 31;
    if (seg >= n_seg) return;

    int v = 0;
    if (lane < G) v = __ldg(map + (long)seg * G + lane);

    const int coloff = lane * 4;
    float4 acc = make_float4(0.f, 0.f, 0.f, 0.f);
#pragma unroll
    for (int j = 0; j < G; j++) {
        int r = __shfl_sync(0xffffffffu, v, j);
        const float4 t = *(const float4*)(in + (long)r * 128 + coloff);
        acc.x += t.x; acc.y += t.y; acc.z += t.z; acc.w += t.w;
    }
    const float sc = 1.0f / (float)G;
    float4 o;
    o.x = fmaxf(acc.x * sc, 0.f);
    o.y = fmaxf(acc.y * sc, 0.f);
    o.z = fmaxf(acc.z * sc, 0.f);
    o.w = fmaxf(acc.w * sc, 0.f);
    if (outf)
        *(float4*)(outf + (long)seg * 128 + coloff) = o;
    if (bfout)
        *(uint2*)(bfout + (long)seg * KD + bf_off + coloff) = to_bf4(o);
}

// ---------------------------------------------------------------------------
// Fused mma.sync GEMM (1 pass x 6 K-chunks of 64) + head.
// smem (dyn, base 1024-aligned at A0):
//   [0,32768)          A chunk double buffer (2 x 128rows x 128B)
//   [32768,98304)      B chunk double buffer (2 x 256rows x 128B)
//   union with  H tile 128x257 f32 [0,131584) + Hp partial [131584,152064)
//   [152064,193024)    W2 256x40 f32;  then b1 (1KB), b2 (256B)
// ---------------------------------------------------------------------------
#define CH_A 16384
#define CH_B 32768
#define OFF_W2 152064
#define OFF_B1 (OFF_W2 + 40960)
#define OFF_B2 (OFF_B1 + 1024)
#define SMEM_DYN (1024 + OFF_B2 + 256)
#define HSTR 257
#define NCHUNK 6

__global__ __launch_bounds__(256, 1)
void mma_head_kernel(const __nv_bfloat16* __restrict__ A,
                     const __nv_bfloat16* __restrict__ B,
                     const float* __restrict__ b1,
                     const float* __restrict__ W2,
                     const float* __restrict__ b2,
                     float* __restrict__ out) {
    extern __shared__ char smem[];
    const uint32_t sb = smem_to_u32(smem);
    const uint32_t A0u = (sb + 1023) & ~1023u;
    char* A0p = smem + (A0u - sb);
    const int tid  = threadIdx.x;
    const int wid  = tid >> 5;
    const int lane = tid & 31;
    const int warp_m = wid >> 2;      // 0..1
    const int warp_n = wid & 3;       // 0..3
    const long rowBase = (long)blockIdx.x * 128;

    float* sW2 = (float*)(A0p + OFF_W2);
    float* sb1 = (float*)(A0p + OFF_B1);
    float* sb2 = (float*)(A0p + OFF_B2);
    {
        const float4* src = (const float4*)W2;
        float4* dst = (float4*)sW2;
#pragma unroll
        for (int i = 0; i < 10; i++) dst[i * 256 + tid] = src[i * 256 + tid];
        sb1[tid] = b1[tid];
        if (tid < 40) sb2[tid] = b2[tid];
    }

    // per-thread cp.async smem targets (swizzled), computed once
    uint32_t a_dst[4], b_dst[8];
    int a_row[4], a_cu[4], b_row[8], b_cu[8];
#pragma unroll
    for (int i = 0; i < 4; i++) {
        int u = i * 256 + tid;
        a_row[i] = u >> 3; a_cu[i] = u & 7;
        a_dst[i] = sw128((uint32_t)(a_row[i] * 128 + a_cu[i] * 16));
    }
#pragma unroll
    for (int i = 0; i < 8; i++) {
        int u = i * 256 + tid;
        b_row[i] = u >> 3; b_cu[i] = u & 7;
        b_dst[i] = sw128((uint32_t)(b_row[i] * 128 + b_cu[i] * 16));
    }

    const uint32_t aoff_base =
        (uint32_t)((warp_m * 64 + (lane & 15)) * 128 + (lane >> 4) * 16);
    const uint32_t boff_base =
        (uint32_t)((warp_n * 64 + (lane & 7) + ((lane >> 4) << 3)) * 128 +
                   ((lane >> 3) & 1) * 16);

    float acc[4][8][4];
#pragma unroll
    for (int mt = 0; mt < 4; mt++)
#pragma unroll
        for (int nt = 0; nt < 8; nt++)
#pragma unroll
            for (int q = 0; q < 4; q++) acc[mt][nt][q] = 0.f;

    // issue chunk 0
    {
        const uint4* asrc = (const uint4*)(A + rowBase * KD);
        const uint4* bsrc = (const uint4*)B;
#pragma unroll
        for (int i = 0; i < 4; i++)
            CP_ASYNC16(A0u + a_dst[i], asrc + a_row[i] * 48 + a_cu[i]);
#pragma unroll
        for (int i = 0; i < 8; i++)
            CP_ASYNC16(A0u + CH_A * 2 + b_dst[i], bsrc + b_row[i] * 48 + b_cu[i]);
        CP_COMMIT();
    }

#pragma unroll 1
    for (int s = 0; s < NCHUNK; s++) {
        CP_WAIT0();
        __syncthreads();
        if (s < NCHUNK - 1) {
            const int kc = s + 1;
            const int buf = kc & 1;
            const uint4* asrc = (const uint4*)(A + rowBase * KD + kc * 64);
            const uint4* bsrc = (const uint4*)(B + kc * 64);
            uint32_t ab = A0u + buf * CH_A;
            uint32_t bb = A0u + CH_A * 2 + buf * CH_B;
#pragma unroll
            for (int i = 0; i < 4; i++)
                CP_ASYNC16(ab + a_dst[i], asrc + a_row[i] * 48 + a_cu[i]);
#pragma unroll
            for (int i = 0; i < 8; i++)
                CP_ASYNC16(bb + b_dst[i], bsrc + b_row[i] * 48 + b_cu[i]);
            CP_COMMIT();
        }
        const uint32_t abase = A0u + (s & 1) * CH_A;
        const uint32_t bbase = A0u + CH_A * 2 + (s & 1) * CH_B;
#pragma unroll
        for (int kk = 0; kk < 4; kk++) {
            unsigned af[4][4];
#pragma unroll
            for (int mt = 0; mt < 4; mt++)
                ldsm_x4(af[mt][0], af[mt][1], af[mt][2], af[mt][3],
                        abase + sw128(aoff_base + (uint32_t)(mt * 2048 + kk * 32)));
#pragma unroll
            for (int ntp = 0; ntp < 4; ntp++) {
                unsigned bf[4];
                ldsm_x4(bf[0], bf[1], bf[2], bf[3],
                        bbase + sw128(boff_base + (uint32_t)(ntp * 2048 + kk * 32)));
#pragma unroll
                for (int mt = 0; mt < 4; mt++) {
                    mma16816(acc[mt][2 * ntp],     af[mt], bf);
                    mma16816(acc[mt][2 * ntp + 1], af[mt], bf + 2);
                }
            }
        }
    }

    // ---- epilogue: acc -> smem H (union over A/B buffers) ----
    __syncthreads();
    float* Hs = (float*)A0p;
    {
        int qr = lane >> 2;
        int qc = (lane & 3) * 2;
#pragma unroll
        for (int mt = 0; mt < 4; mt++) {
            int r0 = warp_m * 64 + mt * 16 + qr;
#pragma unroll
            for (int nt = 0; nt < 8; nt++) {
                int c = warp_n * 64 + nt * 8 + qc;
                Hs[r0 * HSTR + c]           = acc[mt][nt][0];
                Hs[r0 * HSTR + c + 1]       = acc[mt][nt][1];
                Hs[(r0 + 8) * HSTR + c]     = acc[mt][nt][2];
                Hs[(r0 + 8) * HSTR + c + 1] = acc[mt][nt][3];
            }
        }
    }
    __syncthreads();

    // ---- head: relu(H+b1) @ W2, split-K over 2 halves ----
    const int row  = tid & 127;
    const int half = tid >> 7;
    const float* hrow = Hs + row * HSTR + half * 128;
    const float* b1h  = sb1 + half * 128;
    unsigned long long a2[20];
#pragma unroll
    for (int t = 0; t < 20; t++) a2[t] = 0ULL;
#pragma unroll 4
    for (int k = 0; k < 128; k++) {
        float h = fmaxf(hrow[k] + b1h[k], 0.f);
        unsigned long long hh;
        asm("mov.b64 %0, {%1, %1};" : "=l"(hh) : "f"(h));
        const unsigned long long* w2r =
            (const unsigned long long*)(sW2 + (half * 128 + k) * 40);
#pragma unroll
        for (int t = 0; t < 20; t++) fma2(a2[t], hh, w2r[t]);
    }
    unsigned long long* Hp = (unsigned long long*)(A0p + 128 * HSTR * 4);
    if (half == 1) {
#pragma unroll
        for (int t = 0; t < 20; t++) Hp[row * 20 + t] = a2[t];
    }
    __syncthreads();
    if (half == 0 && rowBase + row < N_NODES) {
        float v[40];
#pragma unroll
        for (int t = 0; t < 20; t++) {
            float2 f0 = unpack2(a2[t]);
            float2 f1 = unpack2(Hp[row * 20 + t]);
            v[2 * t]     = f0.x + f1.x + sb2[2 * t];
            v[2 * t + 1] = f0.y + f1.y + sb2[2 * t + 1];
        }
        float m = -1e30f;
#pragma unroll
        for (int c = 0; c < 40; c++) m = fmaxf(m, v[c]);
        float ssum = 0.f;
#pragma unroll
        for (int c = 0; c < 40; c++) ssum += __expf(v[c] - m);
        float lse = m + __logf(ssum);
        float* o = out + (rowBase + row) * 40;
#pragma unroll
        for (int j = 0; j < 10; j++)
            *(float4*)(o + j * 4) = make_float4(v[4 * j] - lse, v[4 * j + 1] - lse,
                                                v[4 * j + 2] - lse, v[4 * j + 3] - lse);
    }
}

// ---------------------------------------------------------------------------
extern "C" void kernel_launch(void* const* d_in, const int* in_sizes, int n_in,
                              void* d_out, int out_size) {
    (void)in_sizes; (void)n_in; (void)out_size;
    const float* node_x    = (const float*)d_in[0];
    const int*   nodes_map = (const int*)d_in[1];
    const int*   edges_map = (const int*)d_in[3];
    const float* W1        = (const float*)d_in[5];
    const float* b1        = (const float*)d_in[6];
    const float* W2        = (const float*)d_in[7];
    const float* b2        = (const float*)d_in[8];
    float*       out       = (float*)d_out;

    float *edgebuf, *nx1;
    __nv_bfloat16 *A, *B;
    cudaGetSymbolAddress((void**)&edgebuf, g_edge);
    cudaGetSymbolAddress((void**)&nx1, g_nx1);
    cudaGetSymbolAddress((void**)&A, g_A);
    cudaGetSymbolAddress((void**)&B, g_B);

    cudaFuncSetAttribute(mma_head_kernel,
                         cudaFuncAttributeMaxDynamicSharedMemorySize, SMEM_DYN);

    // 0) x0 -> A[:,0:128];  W1 fold -> B
    cvt_x_kernel<<<(N_NODES * 32 + 255) / 256, 256>>>(node_x, A);
    prep_w1_kernel<<<(KD * 256 + 255) / 256, 256>>>(W1, B);

    // 1) e1 = relu(mean16(x0[nm]))
    gather_mean_relu<16><<<((long)N_EDGES * 32 + 255) / 256, 256>>>(
        node_x, nodes_map, edgebuf, (__nv_bfloat16*)nullptr, 0, N_EDGES);
    // 2) nx1 = relu(mean8(e1[em]))  -> fp32 nx1 + A[:,128:256]
    gather_mean_relu<8><<<((long)N_NODES * 32 + 255) / 256, 256>>>(
        edgebuf, edges_map, nx1, A, 128, N_NODES);
    // 3) e2b = relu(mean16(nx1[nm]))
    gather_mean_relu<16><<<((long)N_EDGES * 32 + 255) / 256, 256>>>(
        nx1, nodes_map, edgebuf, (__nv_bfloat16*)nullptr, 0, N_EDGES);
    // 4) nx2b -> A[:,256:384] only
    gather_mean_relu<8><<<((long)N_NODES * 32 + 255) / 256, 256>>>(
        edgebuf, edges_map, (float*)nullptr, A, 256, N_NODES);

    // 5) fused 1-pass mma.sync GEMM + head
    mma_head_kernel<<<M_PAD / 128, 256, SMEM_DYN>>>(A, B, b1, W2, b2, out);
}

// round 10
// speedup vs baseline: 3.4104x; 1.0583x over previous
#include <cuda_runtime.h>
#include <cuda_bf16.h>
#include <stdint.h>

// ---------------------------------------------------------------------------
// SHGNN: ALL-bf16 gather chain -> single-pass bf16 mma.sync GEMM fused with
// MLP head (relu+b1, W2, b2, log_softmax; H never leaves smem).
//
// R9 measured: 268.8us, rel_err 3.3e-5 (A bf16 * W1 bf16, 1 MMA pass).
// R10 change: gathers read/write bf16 directly (x0/nx1/nx2b live in A's
// bf16 columns; edge features in a dense bf16 buffer). Halves all gather
// traffic and removes the fp32 intermediates. Predicted rel_err ~1e-4
// (extra bf16 roundings per hop, damped by mean(G) and log_softmax
// common-mode cancellation), total ~195-215us.
// ---------------------------------------------------------------------------

#define N_NODES 100000
#define N_EDGES 50000
#define M_PAD   100096          // 782*128; pad rows stay zero
#define KD      384

__device__ __nv_bfloat16  g_edge[(size_t)N_EDGES * 128];   // e1, then e2b
__device__ __nv_bfloat16  g_A   [(size_t)M_PAD * KD];      // [x0|nx1|nx2b]
__device__ __nv_bfloat16  g_B   [(size_t)256 * KD];        // [n][k]

// ---------------------------------------------------------------------------
__device__ __forceinline__ uint32_t smem_to_u32(const void* p) {
    uint32_t a;
    asm("{ .reg .u64 t; cvta.to.shared.u64 t, %1; cvt.u32.u64 %0, t; }"
        : "=r"(a) : "l"(p));
    return a;
}
__device__ __forceinline__ uint32_t sw128(uint32_t off) {
    return off ^ ((off >> 3) & 0x70);
}
#define CP_ASYNC16(dst, src) \
    asm volatile("cp.async.cg.shared.global [%0], [%1], 16;" \
        :: "r"(dst), "l"(src) : "memory")
#define CP_COMMIT() asm volatile("cp.async.commit_group;" ::: "memory")
#define CP_WAIT0()  asm volatile("cp.async.wait_group 0;" ::: "memory")

__device__ __forceinline__ void ldsm_x4(unsigned& r0, unsigned& r1,
                                        unsigned& r2, unsigned& r3, uint32_t a) {
    asm volatile("ldmatrix.sync.aligned.m8n8.x4.shared.b16 {%0,%1,%2,%3}, [%4];"
        : "=r"(r0), "=r"(r1), "=r"(r2), "=r"(r3) : "r"(a));
}
__device__ __forceinline__ void mma16816(float* c, const unsigned* a,
                                         const unsigned* b) {
    asm volatile(
        "mma.sync.aligned.m16n8k16.row.col.f32.bf16.bf16.f32 "
        "{%0,%1,%2,%3}, {%4,%5,%6,%7}, {%8,%9}, {%0,%1,%2,%3};"
        : "+f"(c[0]), "+f"(c[1]), "+f"(c[2]), "+f"(c[3])
        : "r"(a[0]), "r"(a[1]), "r"(a[2]), "r"(a[3]), "r"(b[0]), "r"(b[1]));
}

// packed f32x2
__device__ __forceinline__ void fma2(unsigned long long& d,
                                     unsigned long long a, unsigned long long b) {
    asm("fma.rn.f32x2 %0, %1, %2, %0;" : "+l"(d) : "l"(a), "l"(b));
}
__device__ __forceinline__ float2 unpack2(unsigned long long v) {
    float2 r;
    asm("mov.b64 {%0, %1}, %2;" : "=f"(r.x), "=f"(r.y) : "l"(v));
    return r;
}
__device__ __forceinline__ uint2 to_bf4(float4 v) {
    __nv_bfloat162 p0 = __floats2bfloat162_rn(v.x, v.y);
    __nv_bfloat162 p1 = __floats2bfloat162_rn(v.z, v.w);
    uint2 r;
    r.x = *reinterpret_cast<unsigned*>(&p0);
    r.y = *reinterpret_cast<unsigned*>(&p1);
    return r;
}
__device__ __forceinline__ float4 bf4_to_f4(uint2 t) {
    __nv_bfloat162 p0 = *reinterpret_cast<__nv_bfloat162*>(&t.x);
    __nv_bfloat162 p1 = *reinterpret_cast<__nv_bfloat162*>(&t.y);
    float2 f0 = __bfloat1622float2(p0);
    float2 f1 = __bfloat1622float2(p1);
    return make_float4(f0.x, f0.y, f1.x, f1.y);
}

// ---------------------------------------------------------------------------
// x0 (fp32) -> A cols [0,128) as bf16
// ---------------------------------------------------------------------------
__global__ void cvt_x_kernel(const float* __restrict__ x,
                             __nv_bfloat16* __restrict__ A) {
    long i = (long)blockIdx.x * blockDim.x + threadIdx.x;
    if (i >= (long)N_NODES * 32) return;
    long r = i >> 5;
    int  c = (int)(i & 31) * 4;
    float4 v = *(const float4*)(x + r * 128 + c);
    *(uint2*)(A + r * KD + c) = to_bf4(v);
}

// ---------------------------------------------------------------------------
// Fold W1 (512->384 rows) + transpose + bf16: B[n][k]
// ---------------------------------------------------------------------------
__global__ void prep_w1_kernel(const float* __restrict__ W1,
                               __nv_bfloat16* __restrict__ B) {
    int idx = blockIdx.x * blockDim.x + threadIdx.x;
    if (idx >= KD * 256) return;
    int k = idx >> 8;
    int n = idx & 255;
    float v;
    if (k < 128)      v = W1[k * 256 + n];
    else if (k < 256) v = W1[k * 256 + n] + W1[(k + 128) * 256 + n];
    else              v = W1[(k + 128) * 256 + n];
    B[(long)n * KD + k] = __float2bfloat16_rn(v);
}

// ---------------------------------------------------------------------------
// bf16 contiguous-segment gather-mean-relu over 128 cols.
// One warp per segment; lane owns 4 columns (uint2 = 4 bf16; warp row
// read = 256B contiguous = 2 L2 sectors). fp32 accumulate, bf16 store.
// ---------------------------------------------------------------------------
template<int G>
__global__ void gather_mean_relu_bf(const __nv_bfloat16* __restrict__ in,
                                    long in_stride, int in_off,
                                    const int* __restrict__ map,
                                    __nv_bfloat16* __restrict__ out,
                                    long out_stride, int out_off,
                                    int n_seg) {
    int seg  = (int)(((long)blockIdx.x * blockDim.x + threadIdx.x) >> 5);
    int lane = threadIdx.x & 31;
    if (seg >= n_seg) return;

    int v = 0;
    if (lane < G) v = __ldg(map + (long)seg * G + lane);

    const int coloff = lane * 4;
    float4 acc = make_float4(0.f, 0.f, 0.f, 0.f);
#pragma unroll
    for (int j = 0; j < G; j++) {
        int r = __shfl_sync(0xffffffffu, v, j);
        uint2 t = *(const uint2*)(in + (long)r * in_stride + in_off + coloff);
        float4 f = bf4_to_f4(t);
        acc.x += f.x; acc.y += f.y; acc.z += f.z; acc.w += f.w;
    }
    const float sc = 1.0f / (float)G;
    float4 o;
    o.x = fmaxf(acc.x * sc, 0.f);
    o.y = fmaxf(acc.y * sc, 0.f);
    o.z = fmaxf(acc.z * sc, 0.f);
    o.w = fmaxf(acc.w * sc, 0.f);
    *(uint2*)(out + (long)seg * out_stride + out_off + coloff) = to_bf4(o);
}

// ---------------------------------------------------------------------------
// Fused mma.sync GEMM (1 pass x 6 K-chunks of 64) + head.
// smem (dyn, base 1024-aligned at A0):
//   [0,32768)          A chunk double buffer (2 x 128rows x 128B)
//   [32768,98304)      B chunk double buffer (2 x 256rows x 128B)
//   union with  H tile 128x257 f32 [0,131584) + Hp partial [131584,152064)
//   [152064,193024)    W2 256x40 f32;  then b1 (1KB), b2 (256B)
// ---------------------------------------------------------------------------
#define CH_A 16384
#define CH_B 32768
#define OFF_W2 152064
#define OFF_B1 (OFF_W2 + 40960)
#define OFF_B2 (OFF_B1 + 1024)
#define SMEM_DYN (1024 + OFF_B2 + 256)
#define HSTR 257
#define NCHUNK 6

__global__ __launch_bounds__(256, 1)
void mma_head_kernel(const __nv_bfloat16* __restrict__ A,
                     const __nv_bfloat16* __restrict__ B,
                     const float* __restrict__ b1,
                     const float* __restrict__ W2,
                     const float* __restrict__ b2,
                     float* __restrict__ out) {
    extern __shared__ char smem[];
    const uint32_t sb = smem_to_u32(smem);
    const uint32_t A0u = (sb + 1023) & ~1023u;
    char* A0p = smem + (A0u - sb);
    const int tid  = threadIdx.x;
    const int wid  = tid >> 5;
    const int lane = tid & 31;
    const int warp_m = wid >> 2;      // 0..1
    const int warp_n = wid & 3;       // 0..3
    const long rowBase = (long)blockIdx.x * 128;

    float* sW2 = (float*)(A0p + OFF_W2);
    float* sb1 = (float*)(A0p + OFF_B1);
    float* sb2 = (float*)(A0p + OFF_B2);
    {
        const float4* src = (const float4*)W2;
        float4* dst = (float4*)sW2;
#pragma unroll
        for (int i = 0; i < 10; i++) dst[i * 256 + tid] = src[i * 256 + tid];
        sb1[tid] = b1[tid];
        if (tid < 40) sb2[tid] = b2[tid];
    }

    // per-thread cp.async smem targets (swizzled), computed once
    uint32_t a_dst[4], b_dst[8];
    int a_row[4], a_cu[4], b_row[8], b_cu[8];
#pragma unroll
    for (int i = 0; i < 4; i++) {
        int u = i * 256 + tid;
        a_row[i] = u >> 3; a_cu[i] = u & 7;
        a_dst[i] = sw128((uint32_t)(a_row[i] * 128 + a_cu[i] * 16));
    }
#pragma unroll
    for (int i = 0; i < 8; i++) {
        int u = i * 256 + tid;
        b_row[i] = u >> 3; b_cu[i] = u & 7;
        b_dst[i] = sw128((uint32_t)(b_row[i] * 128 + b_cu[i] * 16));
    }

    const uint32_t aoff_base =
        (uint32_t)((warp_m * 64 + (lane & 15)) * 128 + (lane >> 4) * 16);
    const uint32_t boff_base =
        (uint32_t)((warp_n * 64 + (lane & 7) + ((lane >> 4) << 3)) * 128 +
                   ((lane >> 3) & 1) * 16);

    float acc[4][8][4];
#pragma unroll
    for (int mt = 0; mt < 4; mt++)
#pragma unroll
        for (int nt = 0; nt < 8; nt++)
#pragma unroll
            for (int q = 0; q < 4; q++) acc[mt][nt][q] = 0.f;

    // issue chunk 0
    {
        const uint4* asrc = (const uint4*)(A + rowBase * KD);
        const uint4* bsrc = (const uint4*)B;
#pragma unroll
        for (int i = 0; i < 4; i++)
            CP_ASYNC16(A0u + a_dst[i], asrc + a_row[i] * 48 + a_cu[i]);
#pragma unroll
        for (int i = 0; i < 8; i++)
            CP_ASYNC16(A0u + CH_A * 2 + b_dst[i], bsrc + b_row[i] * 48 + b_cu[i]);
        CP_COMMIT();
    }

#pragma unroll 1
    for (int s = 0; s < NCHUNK; s++) {
        CP_WAIT0();
        __syncthreads();
        if (s < NCHUNK - 1) {
            const int kc = s + 1;
            const int buf = kc & 1;
            const uint4* asrc = (const uint4*)(A + rowBase * KD + kc * 64);
            const uint4* bsrc = (const uint4*)(B + kc * 64);
            uint32_t ab = A0u + buf * CH_A;
            uint32_t bb = A0u + CH_A * 2 + buf * CH_B;
#pragma unroll
            for (int i = 0; i < 4; i++)
                CP_ASYNC16(ab + a_dst[i], asrc + a_row[i] * 48 + a_cu[i]);
#pragma unroll
            for (int i = 0; i < 8; i++)
                CP_ASYNC16(bb + b_dst[i], bsrc + b_row[i] * 48 + b_cu[i]);
            CP_COMMIT();
        }
        const uint32_t abase = A0u + (s & 1) * CH_A;
        const uint32_t bbase = A0u + CH_A * 2 + (s & 1) * CH_B;
#pragma unroll
        for (int kk = 0; kk < 4; kk++) {
            unsigned af[4][4];
#pragma unroll
            for (int mt = 0; mt < 4; mt++)
                ldsm_x4(af[mt][0], af[mt][1], af[mt][2], af[mt][3],
                        abase + sw128(aoff_base + (uint32_t)(mt * 2048 + kk * 32)));
#pragma unroll
            for (int ntp = 0; ntp < 4; ntp++) {
                unsigned bf[4];
                ldsm_x4(bf[0], bf[1], bf[2], bf[3],
                        bbase + sw128(boff_base + (uint32_t)(ntp * 2048 + kk * 32)));
#pragma unroll
                for (int mt = 0; mt < 4; mt++) {
                    mma16816(acc[mt][2 * ntp],     af[mt], bf);
                    mma16816(acc[mt][2 * ntp + 1], af[mt], bf + 2);
                }
            }
        }
    }

    // ---- epilogue: acc -> smem H (union over A/B buffers) ----
    __syncthreads();
    float* Hs = (float*)A0p;
    {
        int qr = lane >> 2;
        int qc = (lane & 3) * 2;
#pragma unroll
        for (int mt = 0; mt < 4; mt++) {
            int r0 = warp_m * 64 + mt * 16 + qr;
#pragma unroll
            for (int nt = 0; nt < 8; nt++) {
                int c = warp_n * 64 + nt * 8 + qc;
                Hs[r0 * HSTR + c]           = acc[mt][nt][0];
                Hs[r0 * HSTR + c + 1]       = acc[mt][nt][1];
                Hs[(r0 + 8) * HSTR + c]     = acc[mt][nt][2];
                Hs[(r0 + 8) * HSTR + c + 1] = acc[mt][nt][3];
            }
        }
    }
    __syncthreads();

    // ---- head: relu(H+b1) @ W2, split-K over 2 halves ----
    const int row  = tid & 127;
    const int half = tid >> 7;
    const float* hrow = Hs + row * HSTR + half * 128;
    const float* b1h  = sb1 + half * 128;
    unsigned long long a2[20];
#pragma unroll
    for (int t = 0; t < 20; t++) a2[t] = 0ULL;
#pragma unroll 4
    for (int k = 0; k < 128; k++) {
        float h = fmaxf(hrow[k] + b1h[k], 0.f);
        unsigned long long hh;
        asm("mov.b64 %0, {%1, %1};" : "=l"(hh) : "f"(h));
        const unsigned long long* w2r =
            (const unsigned long long*)(sW2 + (half * 128 + k) * 40);
#pragma unroll
        for (int t = 0; t < 20; t++) fma2(a2[t], hh, w2r[t]);
    }
    unsigned long long* Hp = (unsigned long long*)(A0p + 128 * HSTR * 4);
    if (half == 1) {
#pragma unroll
        for (int t = 0; t < 20; t++) Hp[row * 20 + t] = a2[t];
    }
    __syncthreads();
    if (half == 0 && rowBase + row < N_NODES) {
        float v[40];
#pragma unroll
        for (int t = 0; t < 20; t++) {
            float2 f0 = unpack2(a2[t]);
            float2 f1 = unpack2(Hp[row * 20 + t]);
            v[2 * t]     = f0.x + f1.x + sb2[2 * t];
            v[2 * t + 1] = f0.y + f1.y + sb2[2 * t + 1];
        }
        float m = -1e30f;
#pragma unroll
        for (int c = 0; c < 40; c++) m = fmaxf(m, v[c]);
        float ssum = 0.f;
#pragma unroll
        for (int c = 0; c < 40; c++) ssum += __expf(v[c] - m);
        float lse = m + __logf(ssum);
        float* o = out + (rowBase + row) * 40;
#pragma unroll
        for (int j = 0; j < 10; j++)
            *(float4*)(o + j * 4) = make_float4(v[4 * j] - lse, v[4 * j + 1] - lse,
                                                v[4 * j + 2] - lse, v[4 * j + 3] - lse);
    }
}

// ---------------------------------------------------------------------------
extern "C" void kernel_launch(void* const* d_in, const int* in_sizes, int n_in,
                              void* d_out, int out_size) {
    (void)in_sizes; (void)n_in; (void)out_size;
    const float* node_x    = (const float*)d_in[0];
    const int*   nodes_map = (const int*)d_in[1];
    const int*   edges_map = (const int*)d_in[3];
    const float* W1        = (const float*)d_in[5];
    const float* b1        = (const float*)d_in[6];
    const float* W2        = (const float*)d_in[7];
    const float* b2        = (const float*)d_in[8];
    float*       out       = (float*)d_out;

    __nv_bfloat16 *edgebuf, *A, *B;
    cudaGetSymbolAddress((void**)&edgebuf, g_edge);
    cudaGetSymbolAddress((void**)&A, g_A);
    cudaGetSymbolAddress((void**)&B, g_B);

    cudaFuncSetAttribute(mma_head_kernel,
                         cudaFuncAttributeMaxDynamicSharedMemorySize, SMEM_DYN);

    // 0) x0 -> A[:,0:128] (bf16);  W1 fold -> B
    cvt_x_kernel<<<(N_NODES * 32 + 255) / 256, 256>>>(node_x, A);
    prep_w1_kernel<<<(KD * 256 + 255) / 256, 256>>>(W1, B);

    const int gblk16 = (int)(((long)N_EDGES * 32 + 255) / 256);
    const int gblk8  = (int)(((long)N_NODES * 32 + 255) / 256);

    // 1) e1 = relu(mean16(x0_bf[nm]))       : A[:,0:128] -> edgebuf
    gather_mean_relu_bf<16><<<gblk16, 256>>>(
        A, KD, 0, nodes_map, edgebuf, 128, 0, N_EDGES);
    // 2) nx1 = relu(mean8(e1[em]))          : edgebuf -> A[:,128:256]
    gather_mean_relu_bf<8><<<gblk8, 256>>>(
        edgebuf, 128, 0, edges_map, A, KD, 128, N_NODES);
    // 3) e2b = relu(mean16(nx1[nm]))        : A[:,128:256] -> edgebuf (reuse)
    gather_mean_relu_bf<16><<<gblk16, 256>>>(
        A, KD, 128, nodes_map, edgebuf, 128, 0, N_EDGES);
    // 4) nx2b = relu(mean8(e2b[em]))        : edgebuf -> A[:,256:384]
    gather_mean_relu_bf<8><<<gblk8, 256>>>(
        edgebuf, 128, 0, edges_map, A, KD, 256, N_NODES);

    // 5) fused 1-pass mma.sync GEMM + head
    mma_head_kernel<<<M_PAD / 128, 256, SMEM_DYN>>>(A, B, b1, W2, b2, out);
}

// round 11
// speedup vs baseline: 3.6554x; 1.0718x over previous
#include <cuda_runtime.h>
#include <cuda_bf16.h>
#include <stdint.h>

// ---------------------------------------------------------------------------
// SHGNN: all-bf16 gather chain (issue-optimized: uint4 loads, packed f32x2
// accumulate, warp-half row split) -> single-pass bf16 mma.sync GEMM fused
// with MLP head (relu+b1, W2, b2, log_softmax; H never leaves smem).
//
// R10 measured: 254us, rel_err 3.3e-5; gather<8> issue-bound (76.8% issue,
// DRAM 8%). R11: reduce gather issue slots ~25% via 16-lane uint4 rows +
// add.rn.f32x2 accumulation (exact fp32); merge cvt_x+prep_w1 (one launch,
// and makes mma_head the ncu-captured launch #5 next round).
// ---------------------------------------------------------------------------

#define N_NODES 100000
#define N_EDGES 50000
#define M_PAD   100096          // 782*128; pad rows stay zero
#define KD      384

__device__ __nv_bfloat16  g_edge[(size_t)N_EDGES * 128];   // e1, then e2b
__device__ __nv_bfloat16  g_A   [(size_t)M_PAD * KD];      // [x0|nx1|nx2b]
__device__ __nv_bfloat16  g_B   [(size_t)256 * KD];        // [n][k]

// ---------------------------------------------------------------------------
__device__ __forceinline__ uint32_t smem_to_u32(const void* p) {
    uint32_t a;
    asm("{ .reg .u64 t; cvta.to.shared.u64 t, %1; cvt.u32.u64 %0, t; }"
        : "=r"(a) : "l"(p));
    return a;
}
__device__ __forceinline__ uint32_t sw128(uint32_t off) {
    return off ^ ((off >> 3) & 0x70);
}
#define CP_ASYNC16(dst, src) \
    asm volatile("cp.async.cg.shared.global [%0], [%1], 16;" \
        :: "r"(dst), "l"(src) : "memory")
#define CP_COMMIT() asm volatile("cp.async.commit_group;" ::: "memory")
#define CP_WAIT0()  asm volatile("cp.async.wait_group 0;" ::: "memory")

__device__ __forceinline__ void ldsm_x4(unsigned& r0, unsigned& r1,
                                        unsigned& r2, unsigned& r3, uint32_t a) {
    asm volatile("ldmatrix.sync.aligned.m8n8.x4.shared.b16 {%0,%1,%2,%3}, [%4];"
        : "=r"(r0), "=r"(r1), "=r"(r2), "=r"(r3) : "r"(a));
}
__device__ __forceinline__ void mma16816(float* c, const unsigned* a,
                                         const unsigned* b) {
    asm volatile(
        "mma.sync.aligned.m16n8k16.row.col.f32.bf16.bf16.f32 "
        "{%0,%1,%2,%3}, {%4,%5,%6,%7}, {%8,%9}, {%0,%1,%2,%3};"
        : "+f"(c[0]), "+f"(c[1]), "+f"(c[2]), "+f"(c[3])
        : "r"(a[0]), "r"(a[1]), "r"(a[2]), "r"(a[3]), "r"(b[0]), "r"(b[1]));
}

// packed f32x2
#define ADD2(d, s) asm("add.rn.f32x2 %0, %0, %1;" : "+l"(d) : "l"(s))
__device__ __forceinline__ void fma2(unsigned long long& d,
                                     unsigned long long a, unsigned long long b) {
    asm("fma.rn.f32x2 %0, %1, %2, %0;" : "+l"(d) : "l"(a), "l"(b));
}
__device__ __forceinline__ float2 unpack2(unsigned long long v) {
    float2 r;
    asm("mov.b64 {%0, %1}, %2;" : "=f"(r.x), "=f"(r.y) : "l"(v));
    return r;
}
// bf16x2 word -> packed f32x2 (exact: shift/mask expansion)
__device__ __forceinline__ unsigned long long bf2up(unsigned w) {
    unsigned lo = w << 16;
    unsigned hi = w & 0xFFFF0000u;
    unsigned long long r;
    asm("mov.b64 %0, {%1, %2};" : "=l"(r) : "r"(lo), "r"(hi));
    return r;
}
__device__ __forceinline__ uint2 to_bf4(float4 v) {
    __nv_bfloat162 p0 = __floats2bfloat162_rn(v.x, v.y);
    __nv_bfloat162 p1 = __floats2bfloat162_rn(v.z, v.w);
    uint2 r;
    r.x = *reinterpret_cast<unsigned*>(&p0);
    r.y = *reinterpret_cast<unsigned*>(&p1);
    return r;
}

// ---------------------------------------------------------------------------
// Merged prep: x0 (fp32) -> A cols [0,128) bf16  AND  W1 fold/transpose -> B.
// Launch covers both jobs split by linear thread index.
// ---------------------------------------------------------------------------
#define CVT_THREADS ((long)N_NODES * 32)
__global__ void prep_kernel(const float* __restrict__ x,
                            __nv_bfloat16* __restrict__ A,
                            const float* __restrict__ W1,
                            __nv_bfloat16* __restrict__ B) {
    long i = (long)blockIdx.x * blockDim.x + threadIdx.x;
    if (i < CVT_THREADS) {
        long r = i >> 5;
        int  c = (int)(i & 31) * 4;
        float4 v = *(const float4*)(x + r * 128 + c);
        *(uint2*)(A + r * KD + c) = to_bf4(v);
    } else {
        long idx = i - CVT_THREADS;
        if (idx >= (long)KD * 256) return;
        int k = (int)(idx >> 8);
        int n = (int)(idx & 255);
        float v;
        if (k < 128)      v = W1[k * 256 + n];
        else if (k < 256) v = W1[k * 256 + n] + W1[(k + 128) * 256 + n];
        else              v = W1[(k + 128) * 256 + n];
        B[(long)n * KD + k] = __float2bfloat16_rn(v);
    }
}

// ---------------------------------------------------------------------------
// bf16 contiguous-segment gather-mean-relu over 128 cols, issue-optimized.
// Warp = 1 segment. Lanes split into two halves of 16; half h handles rows
// 2j+h; each lane loads uint4 (8 bf16 = one column-octet). Accumulate with
// packed add.rn.f32x2 (exact fp32). Cross-half combine via shfl.bfly 16.
// ---------------------------------------------------------------------------
template<int G, int INS, int OUTS>
__global__ void gather_mean_relu_bf(const __nv_bfloat16* __restrict__ in,
                                    int in_off,
                                    const int* __restrict__ map,
                                    __nv_bfloat16* __restrict__ out,
                                    int out_off, int n_seg) {
    int seg  = (int)(((long)blockIdx.x * blockDim.x + threadIdx.x) >> 5);
    int lane = threadIdx.x & 31;
    if (seg >= n_seg) return;
    const int half = lane >> 4;
    const int pos  = lane & 15;

    int v = 0;
    if (lane < G) v = __ldg(map + (long)seg * G + lane);

    const int coloff = pos * 8;
    unsigned long long a0 = 0, a1 = 0, a2 = 0, a3 = 0;
#pragma unroll
    for (int j = 0; j < G / 2; j++) {
        int r = __shfl_sync(0xffffffffu, v, 2 * j + half);
        uint4 t = *(const uint4*)(in + (long)r * INS + in_off + coloff);
        ADD2(a0, bf2up(t.x));
        ADD2(a1, bf2up(t.y));
        ADD2(a2, bf2up(t.z));
        ADD2(a3, bf2up(t.w));
    }
    // cross-half combine (both halves execute; half 0 stores)
    float2 f0 = unpack2(a0), f1 = unpack2(a1), f2 = unpack2(a2), f3 = unpack2(a3);
    f0.x += __shfl_xor_sync(0xffffffffu, f0.x, 16);
    f0.y += __shfl_xor_sync(0xffffffffu, f0.y, 16);
    f1.x += __shfl_xor_sync(0xffffffffu, f1.x, 16);
    f1.y += __shfl_xor_sync(0xffffffffu, f1.y, 16);
    f2.x += __shfl_xor_sync(0xffffffffu, f2.x, 16);
    f2.y += __shfl_xor_sync(0xffffffffu, f2.y, 16);
    f3.x += __shfl_xor_sync(0xffffffffu, f3.x, 16);
    f3.y += __shfl_xor_sync(0xffffffffu, f3.y, 16);

    if (half == 0) {
        const float sc = 1.0f / (float)G;
        float4 lo, hi;
        lo.x = fmaxf(f0.x * sc, 0.f); lo.y = fmaxf(f0.y * sc, 0.f);
        lo.z = fmaxf(f1.x * sc, 0.f); lo.w = fmaxf(f1.y * sc, 0.f);
        hi.x = fmaxf(f2.x * sc, 0.f); hi.y = fmaxf(f2.y * sc, 0.f);
        hi.z = fmaxf(f3.x * sc, 0.f); hi.w = fmaxf(f3.y * sc, 0.f);
        uint2 p0 = to_bf4(lo);
        uint2 p1 = to_bf4(hi);
        uint4 pk = make_uint4(p0.x, p0.y, p1.x, p1.y);
        *(uint4*)(out + (long)seg * OUTS + out_off + coloff) = pk;
    }
}

// ---------------------------------------------------------------------------
// Fused mma.sync GEMM (1 pass x 6 K-chunks of 64) + head.
// smem (dyn, base 1024-aligned at A0):
//   [0,32768)          A chunk double buffer (2 x 128rows x 128B)
//   [32768,98304)      B chunk double buffer (2 x 256rows x 128B)
//   union with  H tile 128x257 f32 [0,131584) + Hp partial [131584,152064)
//   [152064,193024)    W2 256x40 f32;  then b1 (1KB), b2 (256B)
// ---------------------------------------------------------------------------
#define CH_A 16384
#define CH_B 32768
#define OFF_W2 152064
#define OFF_B1 (OFF_W2 + 40960)
#define OFF_B2 (OFF_B1 + 1024)
#define SMEM_DYN (1024 + OFF_B2 + 256)
#define HSTR 257
#define NCHUNK 6

__global__ __launch_bounds__(256, 1)
void mma_head_kernel(const __nv_bfloat16* __restrict__ A,
                     const __nv_bfloat16* __restrict__ B,
                     const float* __restrict__ b1,
                     const float* __restrict__ W2,
                     const float* __restrict__ b2,
                     float* __restrict__ out) {
    extern __shared__ char smem[];
    const uint32_t sb = smem_to_u32(smem);
    const uint32_t A0u = (sb + 1023) & ~1023u;
    char* A0p = smem + (A0u - sb);
    const int tid  = threadIdx.x;
    const int wid  = tid >> 5;
    const int lane = tid & 31;
    const int warp_m = wid >> 2;      // 0..1
    const int warp_n = wid & 3;       // 0..3
    const long rowBase = (long)blockIdx.x * 128;

    float* sW2 = (float*)(A0p + OFF_W2);
    float* sb1 = (float*)(A0p + OFF_B1);
    float* sb2 = (float*)(A0p + OFF_B2);
    {
        const float4* src = (const float4*)W2;
        float4* dst = (float4*)sW2;
#pragma unroll
        for (int i = 0; i < 10; i++) dst[i * 256 + tid] = src[i * 256 + tid];
        sb1[tid] = b1[tid];
        if (tid < 40) sb2[tid] = b2[tid];
    }

    // per-thread cp.async smem targets (swizzled), computed once
    uint32_t a_dst[4], b_dst[8];
    int a_row[4], a_cu[4], b_row[8], b_cu[8];
#pragma unroll
    for (int i = 0; i < 4; i++) {
        int u = i * 256 + tid;
        a_row[i] = u >> 3; a_cu[i] = u & 7;
        a_dst[i] = sw128((uint32_t)(a_row[i] * 128 + a_cu[i] * 16));
    }
#pragma unroll
    for (int i = 0; i < 8; i++) {
        int u = i * 256 + tid;
        b_row[i] = u >> 3; b_cu[i] = u & 7;
        b_dst[i] = sw128((uint32_t)(b_row[i] * 128 + b_cu[i] * 16));
    }

    const uint32_t aoff_base =
        (uint32_t)((warp_m * 64 + (lane & 15)) * 128 + (lane >> 4) * 16);
    const uint32_t boff_base =
        (uint32_t)((warp_n * 64 + (lane & 7) + ((lane >> 4) << 3)) * 128 +
                   ((lane >> 3) & 1) * 16);

    float acc[4][8][4];
#pragma unroll
    for (int mt = 0; mt < 4; mt++)
#pragma unroll
        for (int nt = 0; nt < 8; nt++)
#pragma unroll
            for (int q = 0; q < 4; q++) acc[mt][nt][q] = 0.f;

    // issue chunk 0
    {
        const uint4* asrc = (const uint4*)(A + rowBase * KD);
        const uint4* bsrc = (const uint4*)B;
#pragma unroll
        for (int i = 0; i < 4; i++)
            CP_ASYNC16(A0u + a_dst[i], asrc + a_row[i] * 48 + a_cu[i]);
#pragma unroll
        for (int i = 0; i < 8; i++)
            CP_ASYNC16(A0u + CH_A * 2 + b_dst[i], bsrc + b_row[i] * 48 + b_cu[i]);
        CP_COMMIT();
    }

#pragma unroll 1
    for (int s = 0; s < NCHUNK; s++) {
        CP_WAIT0();
        __syncthreads();
        if (s < NCHUNK - 1) {
            const int kc = s + 1;
            const int buf = kc & 1;
            const uint4* asrc = (const uint4*)(A + rowBase * KD + kc * 64);
            const uint4* bsrc = (const uint4*)(B + kc * 64);
            uint32_t ab = A0u + buf * CH_A;
            uint32_t bb = A0u + CH_A * 2 + buf * CH_B;
#pragma unroll
            for (int i = 0; i < 4; i++)
                CP_ASYNC16(ab + a_dst[i], asrc + a_row[i] * 48 + a_cu[i]);
#pragma unroll
            for (int i = 0; i < 8; i++)
                CP_ASYNC16(bb + b_dst[i], bsrc + b_row[i] * 48 + b_cu[i]);
            CP_COMMIT();
        }
        const uint32_t abase = A0u + (s & 1) * CH_A;
        const uint32_t bbase = A0u + CH_A * 2 + (s & 1) * CH_B;
#pragma unroll
        for (int kk = 0; kk < 4; kk++) {
            unsigned af[4][4];
#pragma unroll
            for (int mt = 0; mt < 4; mt++)
                ldsm_x4(af[mt][0], af[mt][1], af[mt][2], af[mt][3],
                        abase + sw128(aoff_base + (uint32_t)(mt * 2048 + kk * 32)));
#pragma unroll
            for (int ntp = 0; ntp < 4; ntp++) {
                unsigned bf[4];
                ldsm_x4(bf[0], bf[1], bf[2], bf[3],
                        bbase + sw128(boff_base + (uint32_t)(ntp * 2048 + kk * 32)));
#pragma unroll
                for (int mt = 0; mt < 4; mt++) {
                    mma16816(acc[mt][2 * ntp],     af[mt], bf);
                    mma16816(acc[mt][2 * ntp + 1], af[mt], bf + 2);
                }
            }
        }
    }

    // ---- epilogue: acc -> smem H (union over A/B buffers) ----
    __syncthreads();
    float* Hs = (float*)A0p;
    {
        int qr = lane >> 2;
        int qc = (lane & 3) * 2;
#pragma unroll
        for (int mt = 0; mt < 4; mt++) {
            int r0 = warp_m * 64 + mt * 16 + qr;
#pragma unroll
            for (int nt = 0; nt < 8; nt++) {
                int c = warp_n * 64 + nt * 8 + qc;
                Hs[r0 * HSTR + c]           = acc[mt][nt][0];
                Hs[r0 * HSTR + c + 1]       = acc[mt][nt][1];
                Hs[(r0 + 8) * HSTR + c]     = acc[mt][nt][2];
                Hs[(r0 + 8) * HSTR + c + 1] = acc[mt][nt][3];
            }
        }
    }
    __syncthreads();

    // ---- head: relu(H+b1) @ W2, split-K over 2 halves ----
    const int row  = tid & 127;
    const int half = tid >> 7;
    const float* hrow = Hs + row * HSTR + half * 128;
    const float* b1h  = sb1 + half * 128;
    unsigned long long a2[20];
#pragma unroll
    for (int t = 0; t < 20; t++) a2[t] = 0ULL;
#pragma unroll 4
    for (int k = 0; k < 128; k++) {
        float h = fmaxf(hrow[k] + b1h[k], 0.f);
        unsigned long long hh;
        asm("mov.b64 %0, {%1, %1};" : "=l"(hh) : "f"(h));
        const unsigned long long* w2r =
            (const unsigned long long*)(sW2 + (half * 128 + k) * 40);
#pragma unroll
        for (int t = 0; t < 20; t++) fma2(a2[t], hh, w2r[t]);
    }
    unsigned long long* Hp = (unsigned long long*)(A0p + 128 * HSTR * 4);
    if (half == 1) {
#pragma unroll
        for (int t = 0; t < 20; t++) Hp[row * 20 + t] = a2[t];
    }
    __syncthreads();
    if (half == 0 && rowBase + row < N_NODES) {
        float v[40];
#pragma unroll
        for (int t = 0; t < 20; t++) {
            float2 f0 = unpack2(a2[t]);
            float2 f1 = unpack2(Hp[row * 20 + t]);
            v[2 * t]     = f0.x + f1.x + sb2[2 * t];
            v[2 * t + 1] = f0.y + f1.y + sb2[2 * t + 1];
        }
        float m = -1e30f;
#pragma unroll
        for (int c = 0; c < 40; c++) m = fmaxf(m, v[c]);
        float ssum = 0.f;
#pragma unroll
        for (int c = 0; c < 40; c++) ssum += __expf(v[c] - m);
        float lse = m + __logf(ssum);
        float* o = out + (rowBase + row) * 40;
#pragma unroll
        for (int j = 0; j < 10; j++)
            *(float4*)(o + j * 4) = make_float4(v[4 * j] - lse, v[4 * j + 1] - lse,
                                                v[4 * j + 2] - lse, v[4 * j + 3] - lse);
    }
}

// ---------------------------------------------------------------------------
extern "C" void kernel_launch(void* const* d_in, const int* in_sizes, int n_in,
                              void* d_out, int out_size) {
    (void)in_sizes; (void)n_in; (void)out_size;
    const float* node_x    = (const float*)d_in[0];
    const int*   nodes_map = (const int*)d_in[1];
    const int*   edges_map = (const int*)d_in[3];
    const float* W1        = (const float*)d_in[5];
    const float* b1        = (const float*)d_in[6];
    const float* W2        = (const float*)d_in[7];
    const float* b2        = (const float*)d_in[8];
    float*       out       = (float*)d_out;

    __nv_bfloat16 *edgebuf, *A, *B;
    cudaGetSymbolAddress((void**)&edgebuf, g_edge);
    cudaGetSymbolAddress((void**)&A, g_A);
    cudaGetSymbolAddress((void**)&B, g_B);

    cudaFuncSetAttribute(mma_head_kernel,
                         cudaFuncAttributeMaxDynamicSharedMemorySize, SMEM_DYN);

    // 0) merged: x0 -> A[:,0:128] (bf16) + W1 fold -> B
    {
        long total = CVT_THREADS + (long)KD * 256;
        prep_kernel<<<(int)((total + 255) / 256), 256>>>(node_x, A, W1, B);
    }

    const int gblk16 = (int)(((long)N_EDGES * 32 + 255) / 256);
    const int gblk8  = (int)(((long)N_NODES * 32 + 255) / 256);

    // 1) e1 = relu(mean16(x0_bf[nm]))       : A[:,0:128] -> edgebuf
    gather_mean_relu_bf<16, KD, 128><<<gblk16, 256>>>(
        A, 0, nodes_map, edgebuf, 0, N_EDGES);
    // 2) nx1 = relu(mean8(e1[em]))          : edgebuf -> A[:,128:256]
    gather_mean_relu_bf<8, 128, KD><<<gblk8, 256>>>(
        edgebuf, 0, edges_map, A, 128, N_NODES);
    // 3) e2b = relu(mean16(nx1[nm]))        : A[:,128:256] -> edgebuf (reuse)
    gather_mean_relu_bf<16, KD, 128><<<gblk16, 256>>>(
        A, 128, nodes_map, edgebuf, 0, N_EDGES);
    // 4) nx2b = relu(mean8(e2b[em]))        : edgebuf -> A[:,256:384]
    gather_mean_relu_bf<8, 128, KD><<<gblk8, 256>>>(
        edgebuf, 0, edges_map, A, 256, N_NODES);

    // 5) fused 1-pass mma.sync GEMM + head  (launch #5 -> ncu captures this)
    mma_head_kernel<<<M_PAD / 128, 256, SMEM_DYN>>>(A, B, b1, W2, b2, out);
}

// round 12
// speedup vs baseline: 3.7428x; 1.0239x over previous
#include <cuda_runtime.h>
#include <cuda_bf16.h>
#include <stdint.h>

// ---------------------------------------------------------------------------
// SHGNN: all-bf16 gather chain (2 segments per warp, no cross-half combine)
// -> single-pass bf16 mma.sync GEMM fused with MLP head.
//
// R11: 237us, rel_err 3.3e-5. gather<16> 18.75us issue-bound (57% issue).
// R12: warp = 2 adjacent segments, each owned by a 16-lane half (G sequential
// uint4 row-loads, zero combine shuffles, halved warp count, coalesced
// pair-stores). Exact fp32 math unchanged.
// ---------------------------------------------------------------------------

#define N_NODES 100000
#define N_EDGES 50000
#define M_PAD   100096          // 782*128; pad rows stay zero
#define KD      384

__device__ __nv_bfloat16  g_edge[(size_t)N_EDGES * 128];   // e1, then e2b
__device__ __nv_bfloat16  g_A   [(size_t)M_PAD * KD];      // [x0|nx1|nx2b]
__device__ __nv_bfloat16  g_B   [(size_t)256 * KD];        // [n][k]

// ---------------------------------------------------------------------------
__device__ __forceinline__ uint32_t smem_to_u32(const void* p) {
    uint32_t a;
    asm("{ .reg .u64 t; cvta.to.shared.u64 t, %1; cvt.u32.u64 %0, t; }"
        : "=r"(a) : "l"(p));
    return a;
}
__device__ __forceinline__ uint32_t sw128(uint32_t off) {
    return off ^ ((off >> 3) & 0x70);
}
#define CP_ASYNC16(dst, src) \
    asm volatile("cp.async.cg.shared.global [%0], [%1], 16;" \
        :: "r"(dst), "l"(src) : "memory")
#define CP_COMMIT() asm volatile("cp.async.commit_group;" ::: "memory")
#define CP_WAIT0()  asm volatile("cp.async.wait_group 0;" ::: "memory")

__device__ __forceinline__ void ldsm_x4(unsigned& r0, unsigned& r1,
                                        unsigned& r2, unsigned& r3, uint32_t a) {
    asm volatile("ldmatrix.sync.aligned.m8n8.x4.shared.b16 {%0,%1,%2,%3}, [%4];"
        : "=r"(r0), "=r"(r1), "=r"(r2), "=r"(r3) : "r"(a));
}
__device__ __forceinline__ void mma16816(float* c, const unsigned* a,
                                         const unsigned* b) {
    asm volatile(
        "mma.sync.aligned.m16n8k16.row.col.f32.bf16.bf16.f32 "
        "{%0,%1,%2,%3}, {%4,%5,%6,%7}, {%8,%9}, {%0,%1,%2,%3};"
        : "+f"(c[0]), "+f"(c[1]), "+f"(c[2]), "+f"(c[3])
        : "r"(a[0]), "r"(a[1]), "r"(a[2]), "r"(a[3]), "r"(b[0]), "r"(b[1]));
}

// packed f32x2
#define ADD2(d, s) asm("add.rn.f32x2 %0, %0, %1;" : "+l"(d) : "l"(s))
__device__ __forceinline__ void fma2(unsigned long long& d,
                                     unsigned long long a, unsigned long long b) {
    asm("fma.rn.f32x2 %0, %1, %2, %0;" : "+l"(d) : "l"(a), "l"(b));
}
__device__ __forceinline__ float2 unpack2(unsigned long long v) {
    float2 r;
    asm("mov.b64 {%0, %1}, %2;" : "=f"(r.x), "=f"(r.y) : "l"(v));
    return r;
}
// bf16x2 word -> packed f32x2 (exact: shift/mask expansion)
__device__ __forceinline__ unsigned long long bf2up(unsigned w) {
    unsigned lo = w << 16;
    unsigned hi = w & 0xFFFF0000u;
    unsigned long long r;
    asm("mov.b64 %0, {%1, %2};" : "=l"(r) : "r"(lo), "r"(hi));
    return r;
}
__device__ __forceinline__ uint2 to_bf4(float4 v) {
    __nv_bfloat162 p0 = __floats2bfloat162_rn(v.x, v.y);
    __nv_bfloat162 p1 = __floats2bfloat162_rn(v.z, v.w);
    uint2 r;
    r.x = *reinterpret_cast<unsigned*>(&p0);
    r.y = *reinterpret_cast<unsigned*>(&p1);
    return r;
}

// ---------------------------------------------------------------------------
// Merged prep: x0 (fp32) -> A cols [0,128) bf16  AND  W1 fold/transpose -> B.
// ---------------------------------------------------------------------------
#define CVT_THREADS ((long)N_NODES * 32)
__global__ void prep_kernel(const float* __restrict__ x,
                            __nv_bfloat16* __restrict__ A,
                            const float* __restrict__ W1,
                            __nv_bfloat16* __restrict__ B) {
    long i = (long)blockIdx.x * blockDim.x + threadIdx.x;
    if (i < CVT_THREADS) {
        long r = i >> 5;
        int  c = (int)(i & 31) * 4;
        float4 v = *(const float4*)(x + r * 128 + c);
        *(uint2*)(A + r * KD + c) = to_bf4(v);
    } else {
        long idx = i - CVT_THREADS;
        if (idx >= (long)KD * 256) return;
        int k = (int)(idx >> 8);
        int n = (int)(idx & 255);
        float v;
        if (k < 128)      v = W1[k * 256 + n];
        else if (k < 256) v = W1[k * 256 + n] + W1[(k + 128) * 256 + n];
        else              v = W1[(k + 128) * 256 + n];
        B[(long)n * KD + k] = __float2bfloat16_rn(v);
    }
}

// ---------------------------------------------------------------------------
// bf16 gather-mean-relu over 128 cols: warp = 2 ADJACENT segments.
// Half h (lanes 16h..16h+15) owns segment 2*gw+h entirely: G sequential
// uint4 row loads (pos*8 cols each), packed f32x2 accumulate (exact),
// no cross-half combine, contiguous pair store.
// ---------------------------------------------------------------------------
template<int G, int INS, int OUTS>
__global__ void gather_mean_relu_bf(const __nv_bfloat16* __restrict__ in,
                                    int in_off,
                                    const int* __restrict__ map,
                                    __nv_bfloat16* __restrict__ out,
                                    int out_off, int n_pair) {
    int gw   = (int)(((long)blockIdx.x * blockDim.x + threadIdx.x) >> 5);
    int lane = threadIdx.x & 31;
    if (gw >= n_pair) return;
    const int half = lane >> 4;
    const int pos  = lane & 15;
    const long seg = (long)gw * 2 + half;

    int v = 0;
    if (lane < 2 * G) v = __ldg(map + (long)gw * (2 * G) + lane);

    const int coloff = pos * 8;
    unsigned long long a0 = 0, a1 = 0, a2 = 0, a3 = 0;
#pragma unroll
    for (int j = 0; j < G; j++) {
        int r = __shfl_sync(0xffffffffu, v, half * G + j);
        uint4 t = *(const uint4*)(in + (long)r * INS + in_off + coloff);
        ADD2(a0, bf2up(t.x));
        ADD2(a1, bf2up(t.y));
        ADD2(a2, bf2up(t.z));
        ADD2(a3, bf2up(t.w));
    }
    const float sc = 1.0f / (float)G;
    float2 f0 = unpack2(a0), f1 = unpack2(a1), f2 = unpack2(a2), f3 = unpack2(a3);
    float4 lo, hi;
    lo.x = fmaxf(f0.x * sc, 0.f); lo.y = fmaxf(f0.y * sc, 0.f);
    lo.z = fmaxf(f1.x * sc, 0.f); lo.w = fmaxf(f1.y * sc, 0.f);
    hi.x = fmaxf(f2.x * sc, 0.f); hi.y = fmaxf(f2.y * sc, 0.f);
    hi.z = fmaxf(f3.x * sc, 0.f); hi.w = fmaxf(f3.y * sc, 0.f);
    uint2 p0 = to_bf4(lo);
    uint2 p1 = to_bf4(hi);
    uint4 pk = make_uint4(p0.x, p0.y, p1.x, p1.y);
    *(uint4*)(out + seg * OUTS + out_off + coloff) = pk;
}

// ---------------------------------------------------------------------------
// Fused mma.sync GEMM (1 pass x 6 K-chunks of 64) + head.  (unchanged R11)
// ---------------------------------------------------------------------------
#define CH_A 16384
#define CH_B 32768
#define OFF_W2 152064
#define OFF_B1 (OFF_W2 + 40960)
#define OFF_B2 (OFF_B1 + 1024)
#define SMEM_DYN (1024 + OFF_B2 + 256)
#define HSTR 257
#define NCHUNK 6

__global__ __launch_bounds__(256, 1)
void mma_head_kernel(const __nv_bfloat16* __restrict__ A,
                     const __nv_bfloat16* __restrict__ B,
                     const float* __restrict__ b1,
                     const float* __restrict__ W2,
                     const float* __restrict__ b2,
                     float* __restrict__ out) {
    extern __shared__ char smem[];
    const uint32_t sb = smem_to_u32(smem);
    const uint32_t A0u = (sb + 1023) & ~1023u;
    char* A0p = smem + (A0u - sb);
    const int tid  = threadIdx.x;
    const int wid  = tid >> 5;
    const int lane = tid & 31;
    const int warp_m = wid >> 2;      // 0..1
    const int warp_n = wid & 3;       // 0..3
    const long rowBase = (long)blockIdx.x * 128;

    float* sW2 = (float*)(A0p + OFF_W2);
    float* sb1 = (float*)(A0p + OFF_B1);
    float* sb2 = (float*)(A0p + OFF_B2);
    {
        const float4* src = (const float4*)W2;
        float4* dst = (float4*)sW2;
#pragma unroll
        for (int i = 0; i < 10; i++) dst[i * 256 + tid] = src[i * 256 + tid];
        sb1[tid] = b1[tid];
        if (tid < 40) sb2[tid] = b2[tid];
    }

    uint32_t a_dst[4], b_dst[8];
    int a_row[4], a_cu[4], b_row[8], b_cu[8];
#pragma unroll
    for (int i = 0; i < 4; i++) {
        int u = i * 256 + tid;
        a_row[i] = u >> 3; a_cu[i] = u & 7;
        a_dst[i] = sw128((uint32_t)(a_row[i] * 128 + a_cu[i] * 16));
    }
#pragma unroll
    for (int i = 0; i < 8; i++) {
        int u = i * 256 + tid;
        b_row[i] = u >> 3; b_cu[i] = u & 7;
        b_dst[i] = sw128((uint32_t)(b_row[i] * 128 + b_cu[i] * 16));
    }

    const uint32_t aoff_base =
        (uint32_t)((warp_m * 64 + (lane & 15)) * 128 + (lane >> 4) * 16);
    const uint32_t boff_base =
        (uint32_t)((warp_n * 64 + (lane & 7) + ((lane >> 4) << 3)) * 128 +
                   ((lane >> 3) & 1) * 16);

    float acc[4][8][4];
#pragma unroll
    for (int mt = 0; mt < 4; mt++)
#pragma unroll
        for (int nt = 0; nt < 8; nt++)
#pragma unroll
            for (int q = 0; q < 4; q++) acc[mt][nt][q] = 0.f;

    {
        const uint4* asrc = (const uint4*)(A + rowBase * KD);
        const uint4* bsrc = (const uint4*)B;
#pragma unroll
        for (int i = 0; i < 4; i++)
            CP_ASYNC16(A0u + a_dst[i], asrc + a_row[i] * 48 + a_cu[i]);
#pragma unroll
        for (int i = 0; i < 8; i++)
            CP_ASYNC16(A0u + CH_A * 2 + b_dst[i], bsrc + b_row[i] * 48 + b_cu[i]);
        CP_COMMIT();
    }

#pragma unroll 1
    for (int s = 0; s < NCHUNK; s++) {
        CP_WAIT0();
        __syncthreads();
        if (s < NCHUNK - 1) {
            const int kc = s + 1;
            const int buf = kc & 1;
            const uint4* asrc = (const uint4*)(A + rowBase * KD + kc * 64);
            const uint4* bsrc = (const uint4*)(B + kc * 64);
            uint32_t ab = A0u + buf * CH_A;
            uint32_t bb = A0u + CH_A * 2 + buf * CH_B;
#pragma unroll
            for (int i = 0; i < 4; i++)
                CP_ASYNC16(ab + a_dst[i], asrc + a_row[i] * 48 + a_cu[i]);
#pragma unroll
            for (int i = 0; i < 8; i++)
                CP_ASYNC16(bb + b_dst[i], bsrc + b_row[i] * 48 + b_cu[i]);
            CP_COMMIT();
        }
        const uint32_t abase = A0u + (s & 1) * CH_A;
        const uint32_t bbase = A0u + CH_A * 2 + (s & 1) * CH_B;
#pragma unroll
        for (int kk = 0; kk < 4; kk++) {
            unsigned af[4][4];
#pragma unroll
            for (int mt = 0; mt < 4; mt++)
                ldsm_x4(af[mt][0], af[mt][1], af[mt][2], af[mt][3],
                        abase + sw128(aoff_base + (uint32_t)(mt * 2048 + kk * 32)));
#pragma unroll
            for (int ntp = 0; ntp < 4; ntp++) {
                unsigned bf[4];
                ldsm_x4(bf[0], bf[1], bf[2], bf[3],
                        bbase + sw128(boff_base + (uint32_t)(ntp * 2048 + kk * 32)));
#pragma unroll
                for (int mt = 0; mt < 4; mt++) {
                    mma16816(acc[mt][2 * ntp],     af[mt], bf);
                    mma16816(acc[mt][2 * ntp + 1], af[mt], bf + 2);
                }
            }
        }
    }

    // ---- epilogue: acc -> smem H (union over A/B buffers) ----
    __syncthreads();
    float* Hs = (float*)A0p;
    {
        int qr = lane >> 2;
        int qc = (lane & 3) * 2;
#pragma unroll
        for (int mt = 0; mt < 4; mt++) {
            int r0 = warp_m * 64 + mt * 16 + qr;
#pragma unroll
            for (int nt = 0; nt < 8; nt++) {
                int c = warp_n * 64 + nt * 8 + qc;
                Hs[r0 * HSTR + c]           = acc[mt][nt][0];
                Hs[r0 * HSTR + c + 1]       = acc[mt][nt][1];
                Hs[(r0 + 8) * HSTR + c]     = acc[mt][nt][2];
                Hs[(r0 + 8) * HSTR + c + 1] = acc[mt][nt][3];
            }
        }
    }
    __syncthreads();

    // ---- head: relu(H+b1) @ W2, split-K over 2 halves ----
    const int row  = tid & 127;
    const int half = tid >> 7;
    const float* hrow = Hs + row * HSTR + half * 128;
    const float* b1h  = sb1 + half * 128;
    unsigned long long a2[20];
#pragma unroll
    for (int t = 0; t < 20; t++) a2[t] = 0ULL;
#pragma unroll 4
    for (int k = 0; k < 128; k++) {
        float h = fmaxf(hrow[k] + b1h[k], 0.f);
        unsigned long long hh;
        asm("mov.b64 %0, {%1, %1};" : "=l"(hh) : "f"(h));
        const unsigned long long* w2r =
            (const unsigned long long*)(sW2 + (half * 128 + k) * 40);
#pragma unroll
        for (int t = 0; t < 20; t++) fma2(a2[t], hh, w2r[t]);
    }
    unsigned long long* Hp = (unsigned long long*)(A0p + 128 * HSTR * 4);
    if (half == 1) {
#pragma unroll
        for (int t = 0; t < 20; t++) Hp[row * 20 + t] = a2[t];
    }
    __syncthreads();
    if (half == 0 && rowBase + row < N_NODES) {
        float v[40];
#pragma unroll
        for (int t = 0; t < 20; t++) {
            float2 f0 = unpack2(a2[t]);
            float2 f1 = unpack2(Hp[row * 20 + t]);
            v[2 * t]     = f0.x + f1.x + sb2[2 * t];
            v[2 * t + 1] = f0.y + f1.y + sb2[2 * t + 1];
        }
        float m = -1e30f;
#pragma unroll
        for (int c = 0; c < 40; c++) m = fmaxf(m, v[c]);
        float ssum = 0.f;
#pragma unroll
        for (int c = 0; c < 40; c++) ssum += __expf(v[c] - m);
        float lse = m + __logf(ssum);
        float* o = out + (rowBase + row) * 40;
#pragma unroll
        for (int j = 0; j < 10; j++)
            *(float4*)(o + j * 4) = make_float4(v[4 * j] - lse, v[4 * j + 1] - lse,
                                                v[4 * j + 2] - lse, v[4 * j + 3] - lse);
    }
}

// ---------------------------------------------------------------------------
extern "C" void kernel_launch(void* const* d_in, const int* in_sizes, int n_in,
                              void* d_out, int out_size) {
    (void)in_sizes; (void)n_in; (void)out_size;
    const float* node_x    = (const float*)d_in[0];
    const int*   nodes_map = (const int*)d_in[1];
    const int*   edges_map = (const int*)d_in[3];
    const float* W1        = (const float*)d_in[5];
    const float* b1        = (const float*)d_in[6];
    const float* W2        = (const float*)d_in[7];
    const float* b2        = (const float*)d_in[8];
    float*       out       = (float*)d_out;

    __nv_bfloat16 *edgebuf, *A, *B;
    cudaGetSymbolAddress((void**)&edgebuf, g_edge);
    cudaGetSymbolAddress((void**)&A, g_A);
    cudaGetSymbolAddress((void**)&B, g_B);

    cudaFuncSetAttribute(mma_head_kernel,
                         cudaFuncAttributeMaxDynamicSharedMemorySize, SMEM_DYN);

    // 0) merged: x0 -> A[:,0:128] (bf16) + W1 fold -> B
    {
        long total = CVT_THREADS + (long)KD * 256;
        prep_kernel<<<(int)((total + 255) / 256), 256>>>(node_x, A, W1, B);
    }

    // warp handles 2 segments: warps = n_seg/2 (both counts are even)
    const int gblk16 = (int)(((long)(N_EDGES / 2) * 32 + 255) / 256);
    const int gblk8  = (int)(((long)(N_NODES / 2) * 32 + 255) / 256);

    // 1) e1 = relu(mean16(x0_bf[nm]))       : A[:,0:128] -> edgebuf
    gather_mean_relu_bf<16, KD, 128><<<gblk16, 256>>>(
        A, 0, nodes_map, edgebuf, 0, N_EDGES / 2);
    // 2) nx1 = relu(mean8(e1[em]))          : edgebuf -> A[:,128:256]
    gather_mean_relu_bf<8, 128, KD><<<gblk8, 256>>>(
        edgebuf, 0, edges_map, A, 128, N_NODES / 2);
    // 3) e2b = relu(mean16(nx1[nm]))        : A[:,128:256] -> edgebuf (reuse)
    gather_mean_relu_bf<16, KD, 128><<<gblk16, 256>>>(
        A, 128, nodes_map, edgebuf, 0, N_EDGES / 2);
    // 4) nx2b = relu(mean8(e2b[em]))        : edgebuf -> A[:,256:384]
    gather_mean_relu_bf<8, 128, KD><<<gblk8, 256>>>(
        edgebuf, 0, edges_map, A, 256, N_NODES / 2);

    // 5) fused 1-pass mma.sync GEMM + head
    mma_head_kernel<<<M_PAD / 128, 256, SMEM_DYN>>>(A, B, b1, W2, b2, out);
}

// round 13
// speedup vs baseline: 5.1353x; 1.3720x over previous
#include <cuda_runtime.h>
#include <cuda_bf16.h>
#include <stdint.h>

// ---------------------------------------------------------------------------
// SHGNN: all-bf16 gather chain (2 segments/warp) -> single-pass bf16
// mma.sync GEMM; head (relu+b1, @W2+b2, log_softmax) is a SECOND in-smem
// mma.sync GEMM over bf16 H[128x256] and W2t[48x256] (rows 40-47 zero).
//
// R12: 231.4us, rel_err 3.3e-5; scalar head epilogue ~25-30us of chip time
// (20 LDS.64 + 20 fma2 per k per thread). R13: head-as-MMA: 64 ldsm + 80 mma
// per warp. H stored bf16 (halved STS, no partial buffer). W2->bf16 converted
// post-mainloop into freed chunk smem. Predicted rel_err 5-9e-5.
// ---------------------------------------------------------------------------

#define N_NODES 100000
#define N_EDGES 50000
#define M_PAD   100096          // 782*128; pad rows stay zero (module init)
#define KD      384

__device__ __nv_bfloat16  g_edge[(size_t)N_EDGES * 128];   // e1, then e2b
__device__ __nv_bfloat16  g_A   [(size_t)M_PAD * KD];      // [x0|nx1|nx2b]
__device__ __nv_bfloat16  g_B   [(size_t)256 * KD];        // [n][k]

// ---------------------------------------------------------------------------
__device__ __forceinline__ uint32_t smem_to_u32(const void* p) {
    uint32_t a;
    asm("{ .reg .u64 t; cvta.to.shared.u64 t, %1; cvt.u32.u64 %0, t; }"
        : "=r"(a) : "l"(p));
    return a;
}
__device__ __forceinline__ uint32_t sw128(uint32_t off) {   // 128B rows
    return off ^ ((off >> 3) & 0x70);
}
__device__ __forceinline__ uint32_t swH(uint32_t off) {     // 512B rows
    return off ^ ((off >> 5) & 0x70);
}
#define CP_ASYNC16(dst, src) \
    asm volatile("cp.async.cg.shared.global [%0], [%1], 16;" \
        :: "r"(dst), "l"(src) : "memory")
#define CP_COMMIT() asm volatile("cp.async.commit_group;" ::: "memory")
#define CP_WAIT0()  asm volatile("cp.async.wait_group 0;" ::: "memory")

__device__ __forceinline__ void ldsm_x4(unsigned& r0, unsigned& r1,
                                        unsigned& r2, unsigned& r3, uint32_t a) {
    asm volatile("ldmatrix.sync.aligned.m8n8.x4.shared.b16 {%0,%1,%2,%3}, [%4];"
        : "=r"(r0), "=r"(r1), "=r"(r2), "=r"(r3) : "r"(a));
}
__device__ __forceinline__ void mma16816(float* c, const unsigned* a,
                                         const unsigned* b) {
    asm volatile(
        "mma.sync.aligned.m16n8k16.row.col.f32.bf16.bf16.f32 "
        "{%0,%1,%2,%3}, {%4,%5,%6,%7}, {%8,%9}, {%0,%1,%2,%3};"
        : "+f"(c[0]), "+f"(c[1]), "+f"(c[2]), "+f"(c[3])
        : "r"(a[0]), "r"(a[1]), "r"(a[2]), "r"(a[3]), "r"(b[0]), "r"(b[1]));
}

// packed f32x2 (gathers)
#define ADD2(d, s) asm("add.rn.f32x2 %0, %0, %1;" : "+l"(d) : "l"(s))
__device__ __forceinline__ float2 unpack2(unsigned long long v) {
    float2 r;
    asm("mov.b64 {%0, %1}, %2;" : "=f"(r.x), "=f"(r.y) : "l"(v));
    return r;
}
__device__ __forceinline__ unsigned long long bf2up(unsigned w) {
    unsigned lo = w << 16;
    unsigned hi = w & 0xFFFF0000u;
    unsigned long long r;
    asm("mov.b64 %0, {%1, %2};" : "=l"(r) : "r"(lo), "r"(hi));
    return r;
}
__device__ __forceinline__ uint2 to_bf4(float4 v) {
    __nv_bfloat162 p0 = __floats2bfloat162_rn(v.x, v.y);
    __nv_bfloat162 p1 = __floats2bfloat162_rn(v.z, v.w);
    uint2 r;
    r.x = *reinterpret_cast<unsigned*>(&p0);
    r.y = *reinterpret_cast<unsigned*>(&p1);
    return r;
}
__device__ __forceinline__ unsigned bf2pack(float a, float b) {
    __nv_bfloat162 p = __floats2bfloat162_rn(a, b);
    return *reinterpret_cast<unsigned*>(&p);
}

// ---------------------------------------------------------------------------
// Merged prep: x0 (fp32) -> A cols [0,128) bf16  AND  W1 fold/transpose -> B.
// ---------------------------------------------------------------------------
#define CVT_THREADS ((long)N_NODES * 32)
__global__ void prep_kernel(const float* __restrict__ x,
                            __nv_bfloat16* __restrict__ A,
                            const float* __restrict__ W1,
                            __nv_bfloat16* __restrict__ B) {
    long i = (long)blockIdx.x * blockDim.x + threadIdx.x;
    if (i < CVT_THREADS) {
        long r = i >> 5;
        int  c = (int)(i & 31) * 4;
        float4 v = *(const float4*)(x + r * 128 + c);
        *(uint2*)(A + r * KD + c) = to_bf4(v);
    } else {
        long idx = i - CVT_THREADS;
        if (idx >= (long)KD * 256) return;
        int k = (int)(idx >> 8);
        int n = (int)(idx & 255);
        float v;
        if (k < 128)      v = W1[k * 256 + n];
        else if (k < 256) v = W1[k * 256 + n] + W1[(k + 128) * 256 + n];
        else              v = W1[(k + 128) * 256 + n];
        B[(long)n * KD + k] = __float2bfloat16_rn(v);
    }
}

// ---------------------------------------------------------------------------
// bf16 gather-mean-relu over 128 cols: warp = 2 ADJACENT segments (R12).
// ---------------------------------------------------------------------------
template<int G, int INS, int OUTS>
__global__ void gather_mean_relu_bf(const __nv_bfloat16* __restrict__ in,
                                    int in_off,
                                    const int* __restrict__ map,
                                    __nv_bfloat16* __restrict__ out,
                                    int out_off, int n_pair) {
    int gw   = (int)(((long)blockIdx.x * blockDim.x + threadIdx.x) >> 5);
    int lane = threadIdx.x & 31;
    if (gw >= n_pair) return;
    const int half = lane >> 4;
    const int pos  = lane & 15;
    const long seg = (long)gw * 2 + half;

    int v = 0;
    if (lane < 2 * G) v = __ldg(map + (long)gw * (2 * G) + lane);

    const int coloff = pos * 8;
    unsigned long long a0 = 0, a1 = 0, a2 = 0, a3 = 0;
#pragma unroll
    for (int j = 0; j < G; j++) {
        int r = __shfl_sync(0xffffffffu, v, half * G + j);
        uint4 t = *(const uint4*)(in + (long)r * INS + in_off + coloff);
        ADD2(a0, bf2up(t.x));
        ADD2(a1, bf2up(t.y));
        ADD2(a2, bf2up(t.z));
        ADD2(a3, bf2up(t.w));
    }
    const float sc = 1.0f / (float)G;
    float2 f0 = unpack2(a0), f1 = unpack2(a1), f2 = unpack2(a2), f3 = unpack2(a3);
    float4 lo, hi;
    lo.x = fmaxf(f0.x * sc, 0.f); lo.y = fmaxf(f0.y * sc, 0.f);
    lo.z = fmaxf(f1.x * sc, 0.f); lo.w = fmaxf(f1.y * sc, 0.f);
    hi.x = fmaxf(f2.x * sc, 0.f); hi.y = fmaxf(f2.y * sc, 0.f);
    hi.z = fmaxf(f3.x * sc, 0.f); hi.w = fmaxf(f3.y * sc, 0.f);
    uint2 p0 = to_bf4(lo);
    uint2 p1 = to_bf4(hi);
    uint4 pk = make_uint4(p0.x, p0.y, p1.x, p1.y);
    *(uint4*)(out + seg * OUTS + out_off + coloff) = pk;
}

// ---------------------------------------------------------------------------
// Fused mma.sync GEMM (6 K-chunks of 64) + MMA head.
// smem (dyn, 1024-aligned at A0):
//   mainloop:  A chunks 2x16K [0,32768) ; B chunks 2x32K [32768,98304)
//   epilogue (union of the above):
//     H bf16 128x256, 512B rows, swH     [0,65536)
//     W2t bf16 48x256, 512B rows, swH    [65536,90112)
//   persistent: b1 f32 [98304,99328) ; b2 f32 [99328,99488)
// ---------------------------------------------------------------------------
#define CH_A 16384
#define CH_B 32768
#define OFF_W2T 65536
#define OFF_B1 98304
#define OFF_B2 99328
#define SMEM_DYN (1024 + 99584)
#define NCHUNK 6

__global__ __launch_bounds__(256, 1)
void mma_head_kernel(const __nv_bfloat16* __restrict__ A,
                     const __nv_bfloat16* __restrict__ B,
                     const float* __restrict__ b1,
                     const float* __restrict__ W2,
                     const float* __restrict__ b2,
                     float* __restrict__ out) {
    extern __shared__ char smem[];
    const uint32_t sb = smem_to_u32(smem);
    const uint32_t A0u = (sb + 1023) & ~1023u;
    char* A0p = smem + (A0u - sb);
    const int tid  = threadIdx.x;
    const int wid  = tid >> 5;
    const int lane = tid & 31;
    const int warp_m = wid >> 2;      // 0..1
    const int warp_n = wid & 3;       // 0..3
    const long rowBase = (long)blockIdx.x * 128;

    float* sb1 = (float*)(A0p + OFF_B1);
    float* sb2 = (float*)(A0p + OFF_B2);
    sb1[tid] = b1[tid];
    if (tid < 40) sb2[tid] = b2[tid];

    // per-thread cp.async smem targets (swizzled), computed once
    uint32_t a_dst[4], b_dst[8];
    int a_row[4], a_cu[4], b_row[8], b_cu[8];
#pragma unroll
    for (int i = 0; i < 4; i++) {
        int u = i * 256 + tid;
        a_row[i] = u >> 3; a_cu[i] = u & 7;
        a_dst[i] = sw128((uint32_t)(a_row[i] * 128 + a_cu[i] * 16));
    }
#pragma unroll
    for (int i = 0; i < 8; i++) {
        int u = i * 256 + tid;
        b_row[i] = u >> 3; b_cu[i] = u & 7;
        b_dst[i] = sw128((uint32_t)(b_row[i] * 128 + b_cu[i] * 16));
    }

    const uint32_t aoff_base =
        (uint32_t)((warp_m * 64 + (lane & 15)) * 128 + (lane >> 4) * 16);
    const uint32_t boff_base =
        (uint32_t)((warp_n * 64 + (lane & 7) + ((lane >> 4) << 3)) * 128 +
                   ((lane >> 3) & 1) * 16);

    float acc[4][8][4];
#pragma unroll
    for (int mt = 0; mt < 4; mt++)
#pragma unroll
        for (int nt = 0; nt < 8; nt++)
#pragma unroll
            for (int q = 0; q < 4; q++) acc[mt][nt][q] = 0.f;

    // issue chunk 0
    {
        const uint4* asrc = (const uint4*)(A + rowBase * KD);
        const uint4* bsrc = (const uint4*)B;
#pragma unroll
        for (int i = 0; i < 4; i++)
            CP_ASYNC16(A0u + a_dst[i], asrc + a_row[i] * 48 + a_cu[i]);
#pragma unroll
        for (int i = 0; i < 8; i++)
            CP_ASYNC16(A0u + CH_A * 2 + b_dst[i], bsrc + b_row[i] * 48 + b_cu[i]);
        CP_COMMIT();
    }

#pragma unroll 1
    for (int s = 0; s < NCHUNK; s++) {
        CP_WAIT0();
        __syncthreads();
        if (s < NCHUNK - 1) {
            const int kc = s + 1;
            const int buf = kc & 1;
            const uint4* asrc = (const uint4*)(A + rowBase * KD + kc * 64);
            const uint4* bsrc = (const uint4*)(B + kc * 64);
            uint32_t ab = A0u + buf * CH_A;
            uint32_t bb = A0u + CH_A * 2 + buf * CH_B;
#pragma unroll
            for (int i = 0; i < 4; i++)
                CP_ASYNC16(ab + a_dst[i], asrc + a_row[i] * 48 + a_cu[i]);
#pragma unroll
            for (int i = 0; i < 8; i++)
                CP_ASYNC16(bb + b_dst[i], bsrc + b_row[i] * 48 + b_cu[i]);
            CP_COMMIT();
        }
        const uint32_t abase = A0u + (s & 1) * CH_A;
        const uint32_t bbase = A0u + CH_A * 2 + (s & 1) * CH_B;
#pragma unroll
        for (int kk = 0; kk < 4; kk++) {
            unsigned af[4][4];
#pragma unroll
            for (int mt = 0; mt < 4; mt++)
                ldsm_x4(af[mt][0], af[mt][1], af[mt][2], af[mt][3],
                        abase + sw128(aoff_base + (uint32_t)(mt * 2048 + kk * 32)));
#pragma unroll
            for (int ntp = 0; ntp < 4; ntp++) {
                unsigned bf[4];
                ldsm_x4(bf[0], bf[1], bf[2], bf[3],
                        bbase + sw128(boff_base + (uint32_t)(ntp * 2048 + kk * 32)));
#pragma unroll
                for (int mt = 0; mt < 4; mt++) {
                    mma16816(acc[mt][2 * ntp],     af[mt], bf);
                    mma16816(acc[mt][2 * ntp + 1], af[mt], bf + 2);
                }
            }
        }
    }

    // ---- epilogue 1: acc -> bf16 H (union over chunk buffers), + W2t ----
    __syncthreads();
    {
        int qr = lane >> 2;
        int qc = (lane & 3) * 2;
#pragma unroll
        for (int mt = 0; mt < 4; mt++) {
            int r0 = warp_m * 64 + mt * 16 + qr;
#pragma unroll
            for (int nt = 0; nt < 8; nt++) {
                int c = warp_n * 64 + nt * 8 + qc;
                float b0 = sb1[c], b1v = sb1[c + 1];
                float h0 = fmaxf(acc[mt][nt][0] + b0, 0.f);
                float h1 = fmaxf(acc[mt][nt][1] + b1v, 0.f);
                float h2 = fmaxf(acc[mt][nt][2] + b0, 0.f);
                float h3 = fmaxf(acc[mt][nt][3] + b1v, 0.f);
                *(unsigned*)(A0p + swH((uint32_t)(r0 * 512 + c * 2))) =
                    bf2pack(h0, h1);
                *(unsigned*)(A0p + swH((uint32_t)((r0 + 8) * 512 + c * 2))) =
                    bf2pack(h2, h3);
            }
        }
    }
    // W2 (fp32, L2-hot) -> W2t bf16 [48][256], rows 40..47 zero
#pragma unroll 4
    for (int i = 0; i < 48; i++) {
        float v = (i < 40) ? __ldg(W2 + tid * 40 + i) : 0.f;
        *(__nv_bfloat16*)(A0p + OFF_W2T + swH((uint32_t)(i * 512 + tid * 2))) =
            __float2bfloat16_rn(v);
    }
    __syncthreads();

    // ---- epilogue 2: head MMA  logits[128,40] = H @ W2t^T ----
    {
        const uint32_t hbase = A0u;
        const uint32_t wbase = A0u + OFF_W2T;
        const uint32_t aoff0 =
            (uint32_t)((wid * 16 + (lane & 15)) * 512 + (lane >> 4) * 16);
        const uint32_t boff0 =
            (uint32_t)(((lane & 7) + ((lane >> 4) << 3)) * 512 +
                       ((lane >> 3) & 1) * 16);
        float hacc[5][4];
#pragma unroll
        for (int t = 0; t < 5; t++)
#pragma unroll
            for (int q = 0; q < 4; q++) hacc[t][q] = 0.f;

#pragma unroll
        for (int kk = 0; kk < 16; kk++) {
            unsigned af[4];
            ldsm_x4(af[0], af[1], af[2], af[3],
                    hbase + swH(aoff0 + (uint32_t)(kk * 32)));
#pragma unroll
            for (int tp = 0; tp < 3; tp++) {
                unsigned bf[4];
                ldsm_x4(bf[0], bf[1], bf[2], bf[3],
                        wbase + swH(boff0 + (uint32_t)(tp * 8192 + kk * 32)));
                mma16816(hacc[2 * tp], af, bf);
                if (tp < 2) mma16816(hacc[2 * tp + 1], af, bf + 2);
            }
        }

        // log-softmax over 40 cols; row r cols live on 4 lanes (lane&3)
        int qc2 = (lane & 3) * 2;
        float v0[10], v1[10];
#pragma unroll
        for (int t = 0; t < 5; t++) {
            int c = t * 8 + qc2;
            v0[2 * t]     = hacc[t][0] + sb2[c];
            v0[2 * t + 1] = hacc[t][1] + sb2[c + 1];
            v1[2 * t]     = hacc[t][2] + sb2[c];
            v1[2 * t + 1] = hacc[t][3] + sb2[c + 1];
        }
        float m0 = -1e30f, m1 = -1e30f;
#pragma unroll
        for (int i = 0; i < 10; i++) {
            m0 = fmaxf(m0, v0[i]);
            m1 = fmaxf(m1, v1[i]);
        }
        m0 = fmaxf(m0, __shfl_xor_sync(0xffffffffu, m0, 1));
        m0 = fmaxf(m0, __shfl_xor_sync(0xffffffffu, m0, 2));
        m1 = fmaxf(m1, __shfl_xor_sync(0xffffffffu, m1, 1));
        m1 = fmaxf(m1, __shfl_xor_sync(0xffffffffu, m1, 2));
        float s0 = 0.f, s1 = 0.f;
#pragma unroll
        for (int i = 0; i < 10; i++) {
            s0 += __expf(v0[i] - m0);
            s1 += __expf(v1[i] - m1);
        }
        s0 += __shfl_xor_sync(0xffffffffu, s0, 1);
        s0 += __shfl_xor_sync(0xffffffffu, s0, 2);
        s1 += __shfl_xor_sync(0xffffffffu, s1, 1);
        s1 += __shfl_xor_sync(0xffffffffu, s1, 2);
        float lse0 = m0 + __logf(s0);
        float lse1 = m1 + __logf(s1);

        long r0 = rowBase + wid * 16 + (lane >> 2);
        if (r0 < N_NODES) {
            float* o = out + r0 * 40;
#pragma unroll
            for (int t = 0; t < 5; t++) {
                float2 w = make_float2(v0[2 * t] - lse0, v0[2 * t + 1] - lse0);
                *(float2*)(o + t * 8 + qc2) = w;
            }
        }
        long r1 = r0 + 8;
        if (r1 < N_NODES) {
            float* o = out + r1 * 40;
#pragma unroll
            for (int t = 0; t < 5; t++) {
                float2 w = make_float2(v1[2 * t] - lse1, v1[2 * t + 1] - lse1);
                *(float2*)(o + t * 8 + qc2) = w;
            }
        }
    }
}

// ---------------------------------------------------------------------------
extern "C" void kernel_launch(void* const* d_in, const int* in_sizes, int n_in,
                              void* d_out, int out_size) {
    (void)in_sizes; (void)n_in; (void)out_size;
    const float* node_x    = (const float*)d_in[0];
    const int*   nodes_map = (const int*)d_in[1];
    const int*   edges_map = (const int*)d_in[3];
    const float* W1        = (const float*)d_in[5];
    const float* b1        = (const float*)d_in[6];
    const float* W2        = (const float*)d_in[7];
    const float* b2        = (const float*)d_in[8];
    float*       out       = (float*)d_out;

    __nv_bfloat16 *edgebuf, *A, *B;
    cudaGetSymbolAddress((void**)&edgebuf, g_edge);
    cudaGetSymbolAddress((void**)&A, g_A);
    cudaGetSymbolAddress((void**)&B, g_B);

    cudaFuncSetAttribute(mma_head_kernel,
                         cudaFuncAttributeMaxDynamicSharedMemorySize, SMEM_DYN);

    // 0) merged: x0 -> A[:,0:128] (bf16) + W1 fold -> B
    {
        long total = CVT_THREADS + (long)KD * 256;
        prep_kernel<<<(int)((total + 255) / 256), 256>>>(node_x, A, W1, B);
    }

    // warp handles 2 segments: warps = n_seg/2
    const int gblk16 = (int)(((long)(N_EDGES / 2) * 32 + 255) / 256);
    const int gblk8  = (int)(((long)(N_NODES / 2) * 32 + 255) / 256);

    // 1) e1 = relu(mean16(x0_bf[nm]))       : A[:,0:128] -> edgebuf
    gather_mean_relu_bf<16, KD, 128><<<gblk16, 256>>>(
        A, 0, nodes_map, edgebuf, 0, N_EDGES / 2);
    // 2) nx1 = relu(mean8(e1[em]))          : edgebuf -> A[:,128:256]
    gather_mean_relu_bf<8, 128, KD><<<gblk8, 256>>>(
        edgebuf, 0, edges_map, A, 128, N_NODES / 2);
    // 3) e2b = relu(mean16(nx1[nm]))        : A[:,128:256] -> edgebuf (reuse)
    gather_mean_relu_bf<16, KD, 128><<<gblk16, 256>>>(
        A, 128, nodes_map, edgebuf, 0, N_EDGES / 2);
    // 4) nx2b = relu(mean8(e2b[em]))        : edgebuf -> A[:,256:384]
    gather_mean_relu_bf<8, 128, KD><<<gblk8, 256>>>(
        edgebuf, 0, edges_map, A, 256, N_NODES / 2);

    // 5) fused 1-pass mma.sync GEMM + MMA head
    mma_head_kernel<<<M_PAD / 128, 256, SMEM_DYN>>>(A, B, b1, W2, b2, out);
}